// round 14
// baseline (speedup 1.0000x reference)
#include <cuda_runtime.h>
#include <cuda_fp16.h>
#include <math.h>
#include <stdint.h>

#define B_ 4
#define T_ 2048
#define C_ 1024
#define H_ 128
#define E_ 16
#define N_ (B_*T_)   /* 8192 tokens */

// ---------------- scratch (allocation-free: __device__ globals) ----------------
__device__ float g_q[(size_t)N_*H_];
__device__ float g_k[(size_t)N_*H_];
__device__ float g_v[(size_t)N_*H_];
__device__ float g_o[(size_t)N_*H_];
__device__ float g_S[(size_t)B_*T_*T_];          // 64 MB f32 scores

__device__ half g_xh[(size_t)N_*C_],  g_xl[(size_t)N_*C_];
__device__ half g_qh[(size_t)N_*H_],  g_ql[(size_t)N_*H_];
__device__ half g_kh[(size_t)N_*H_];
__device__ half g_vTh[(size_t)N_*H_];                         // [B][H][T]
__device__ half g_oh[(size_t)N_*H_],  g_ol[(size_t)N_*H_];
__device__ half g_Sh[(size_t)B_*T_*T_], g_Sl[(size_t)B_*T_*T_];
__device__ half g_wqh[(size_t)E_*H_*C_];                      // [E][H][C]
__device__ half g_wkh[(size_t)E_*H_*C_];
__device__ half g_wvh[(size_t)E_*H_*C_];
__device__ half g_woh[(size_t)E_*C_*H_];                      // [E][C][H]

__device__ int   g_cnt[E_];
__device__ int   g_idx[(size_t)E_*N_];
__device__ float g_wt[(size_t)E_*N_];
__device__ float g_invsn[E_];
__device__ float g_sig[E_];

// ---------------- mma.sync / ldmatrix / cp.async helpers (baseline PTX) ---------
#define MMA16816(d, A0, A1, A2, A3, Bv0, Bv1) \
    asm volatile("mma.sync.aligned.m16n8k16.row.col.f32.f16.f16.f32 " \
        "{%0,%1,%2,%3},{%4,%5,%6,%7},{%8,%9},{%0,%1,%2,%3};" \
        : "+f"((d)[0]), "+f"((d)[1]), "+f"((d)[2]), "+f"((d)[3]) \
        : "r"(A0), "r"(A1), "r"(A2), "r"(A3), "r"(Bv0), "r"(Bv1))

#define LDSM4(r0, r1, r2, r3, addr) \
    asm volatile("ldmatrix.sync.aligned.m8n8.x4.shared.b16 {%0,%1,%2,%3}, [%4];" \
        : "=r"(r0), "=r"(r1), "=r"(r2), "=r"(r3) : "r"(addr))

#define CPA16(dst, src) \
    asm volatile("cp.async.cg.shared.global [%0], [%1], 16;" :: "r"(dst), "l"(src))

__device__ __forceinline__ uint32_t smem_u32(const void* p) {
    uint32_t a;
    asm("{ .reg .u64 t; cvta.to.shared.u64 t, %1; cvt.u32.u64 %0, t; }" : "=r"(a) : "l"(p));
    return a;
}

__device__ __forceinline__ void split_f32(float v, half& h, half& l) {
    h = __float2half_rn(v);
    l = __float2half_rn(v - __half2float(h));
}

// ---------------- HMMA GEMM (2-term fp16: D = (Ah+Al) * Bh) ----------------------
// CTA tile 128(m) x 64(n), k-chunk 32, warp grid 4m x 2n (warp tile 32x32)
struct TCArgs {
    const half *Ah, *Al;
    const half *Bh0, *Bh1, *Bh2;
    float *C0, *C1, *C2;
    long sAz, sBz, sCz;
    int  lda, ldb, ldc;
    int  M, K, nxb, nsplit, ksplit;
    float alpha;
    const int* cnt; const int* idxB; const float* wtB;
};

#define PITCH 20                     /* row pitch in b32: 16 (32 fp16) + 4 pad */
#define A_SZ  (128*PITCH*4)          /* 10240 B per A tile */
#define B_SZ  (64*PITCH*4)           /* 5120 B per B tile */
#define STG_B (2*A_SZ + B_SZ)        /* 25600 B per stage */
#define DSM_BYTES (2*STG_B)          /* 51200 B */

template<bool GATHER, bool ATOMIC>
__global__ void __launch_bounds__(256, 3) hm_gemm(TCArgs a)
{
    int zb  = blockIdx.z / a.nsplit;
    int sp  = blockIdx.z % a.nsplit;
    int mat = blockIdx.x / a.nxb;
    int n0  = (blockIdx.x % a.nxb) * 64;

    int Mz = a.M;
    const int*   gidx = nullptr;
    const float* gwt  = nullptr;
    if (GATHER) {
        Mz   = a.cnt[zb];
        gidx = a.idxB + (size_t)zb * N_;
        gwt  = a.wtB  + (size_t)zb * N_;
    }
    int m0 = blockIdx.y * 128;
    if (m0 >= Mz) return;

    const half* Ah = a.Ah + (size_t)zb * a.sAz;
    const half* Al = a.Al + (size_t)zb * a.sAz;
    const half* Bh = (mat == 0 ? a.Bh0 : mat == 1 ? a.Bh1 : a.Bh2) + (size_t)zb * a.sBz;
    float*      C  = (mat == 0 ? a.C0  : mat == 1 ? a.C1  : a.C2)  + (size_t)zb * a.sCz;

    extern __shared__ uint32_t dsm[];
    uint32_t smbase = smem_u32(dsm);

    __shared__ int   s_idx[128];
    __shared__ float s_wt[128];

    int tid  = threadIdx.x;
    int lane = tid & 31, wid = tid >> 5;
    int g = lane >> 2, t = lane & 3;
    int wm = wid & 3, wn = wid >> 2;          // warp grid 4 (m) x 2 (n)
    int mbw = wm * 32, nbw = wn * 32;

    if (GATHER) {
        for (int i = tid; i < 128; i += 256) {
            int r = m0 + i;
            bool v = r < Mz;
            s_idx[i] = v ? gidx[r] : 0;
            s_wt[i]  = v ? gwt[r] : 0.f;
        }
    }
    __syncthreads();

    float acc[2][4][4];
    #pragma unroll
    for (int i = 0; i < 2; i++)
        #pragma unroll
        for (int j = 0; j < 4; j++)
            #pragma unroll
            for (int c = 0; c < 4; c++) acc[i][j][c] = 0.f;

    int kb = sp * a.ksplit;
    int ke = kb + a.ksplit; if (ke > a.K) ke = a.K;
    int nch = (ke - kb) >> 5;

    // per-thread global load coordinates (fixed across k-chunks)
    int f0row = tid >> 2,          f0kq = tid & 3;          // A rows 0..63
    int f1row = (tid + 256) >> 2,  f1kq = (tid + 256) & 3;  // A rows 64..127
    int fbrow = tid >> 2,          fbkq = tid & 3;          // B rows 0..63
    long ar0 = GATHER ? (long)s_idx[f0row] : (long)(m0 + f0row);
    long ar1 = GATHER ? (long)s_idx[f1row] : (long)(m0 + f1row);
    long brB = (long)(n0 + fbrow);
    uint32_t soA0 = (uint32_t)(f0row * PITCH + f0kq * 4) * 4u;
    uint32_t soA1 = (uint32_t)(f1row * PITCH + f1kq * 4) * 4u;
    uint32_t soB  = (uint32_t)(fbrow * PITCH + fbkq * 4) * 4u;

    // ldmatrix lane-address offsets (bytes)
    int jj = lane >> 3, rr = lane & 7;
    uint32_t aoff = (uint32_t)(((jj & 1) * 8 + rr) * PITCH + (jj >> 1) * 4) * 4u;
    uint32_t boff = (uint32_t)(((jj >> 1) * 8 + rr) * PITCH + (jj & 1) * 4) * 4u;
    uint32_t baseA = smbase + (uint32_t)(mbw * PITCH) * 4u + aoff;
    uint32_t baseB = smbase + (uint32_t)(2*A_SZ) + (uint32_t)(nbw * PITCH) * 4u + boff;

    // chunk loader: 5 cp.async of 16B into stage s (tiles: Ah, Al, Bh)
    auto load_chunk = [&](int k0, int s) {
        uint32_t bb = (uint32_t)s * (uint32_t)STG_B;
        CPA16(smbase + bb + soA0,         Ah + ar0 * (long)a.lda + k0 + f0kq * 8);
        CPA16(smbase + bb + A_SZ + soA0,  Al + ar0 * (long)a.lda + k0 + f0kq * 8);
        CPA16(smbase + bb + soA1,         Ah + ar1 * (long)a.lda + k0 + f1kq * 8);
        CPA16(smbase + bb + A_SZ + soA1,  Al + ar1 * (long)a.lda + k0 + f1kq * 8);
        CPA16(smbase + bb + 2*A_SZ + soB, Bh + brB * (long)a.ldb + k0 + fbkq * 8);
    };

    load_chunk(kb, 0);
    asm volatile("cp.async.commit_group;" ::: "memory");

    for (int i = 0; i < nch; i++) {
        if (i + 1 < nch) {
            load_chunk(kb + (i + 1) * 32, (i + 1) & 1);
            asm volatile("cp.async.commit_group;" ::: "memory");
            asm volatile("cp.async.wait_group 1;" ::: "memory");
        } else {
            asm volatile("cp.async.wait_group 0;" ::: "memory");
        }
        __syncthreads();

        uint32_t bb = (uint32_t)(i & 1) * (uint32_t)STG_B;
        uint32_t bAh = baseA + bb, bAl = baseA + bb + A_SZ;
        uint32_t bBh = baseB + bb;

        #pragma unroll
        for (int kk = 0; kk < 2; kk++) {
            uint32_t kadd = (uint32_t)(kk * 8) * 4u;
            uint32_t bh[4][2];
            #pragma unroll
            for (int np = 0; np < 2; np++) {
                uint32_t ba = (uint32_t)(np * 16 * PITCH) * 4u + kadd;
                LDSM4(bh[2*np][0], bh[2*np][1], bh[2*np+1][0], bh[2*np+1][1], bBh + ba);
            }
            #pragma unroll
            for (int mt = 0; mt < 2; mt++) {
                uint32_t ma = (uint32_t)(mt * 16 * PITCH) * 4u + kadd;
                uint32_t ah0, ah1, ah2, ah3, al0, al1, al2, al3;
                LDSM4(ah0, ah1, ah2, ah3, bAh + ma);
                LDSM4(al0, al1, al2, al3, bAl + ma);
                #pragma unroll
                for (int nt = 0; nt < 4; nt++) {
                    MMA16816(acc[mt][nt], ah0, ah1, ah2, ah3, bh[nt][0], bh[nt][1]);
                    MMA16816(acc[mt][nt], al0, al1, al2, al3, bh[nt][0], bh[nt][1]);
                }
            }
        }
        __syncthreads();
    }

    // epilogue: c0,c1 -> row (g), cols 2t,2t+1 ; c2,c3 -> row (g+8)
    #pragma unroll
    for (int mt = 0; mt < 2; mt++) {
        #pragma unroll
        for (int half_ = 0; half_ < 2; half_++) {
            int lr = mbw + mt * 16 + g + half_ * 8;
            bool rv; long orow; float sc;
            if (GATHER) { rv = (m0 + lr) < Mz; orow = s_idx[lr]; sc = a.alpha * s_wt[lr]; }
            else        { rv = true;           orow = m0 + lr;   sc = a.alpha; }
            if (rv) {
                float* cp = C + orow * (long)a.ldc + n0 + nbw;
                #pragma unroll
                for (int nt = 0; nt < 4; nt++) {
                    int col = nt * 8 + 2 * t;
                    float v0 = acc[mt][nt][half_ * 2 + 0] * sc;
                    float v1 = acc[mt][nt][half_ * 2 + 1] * sc;
                    if (ATOMIC) { atomicAdd(cp + col, v0); atomicAdd(cp + col + 1, v1); }
                    else        { float2 vv; vv.x = v0; vv.y = v1; *(float2*)(cp + col) = vv; }
                }
            }
        }
    }
}

// ---------------- sim-matrix column norms + sigmoid(gates) + counter reset -------
__global__ void prep_kernel(const float* __restrict__ sim, const float* __restrict__ gates) {
    int e = threadIdx.x >> 5, lane = threadIdx.x & 31;
    if (threadIdx.x < E_) g_cnt[threadIdx.x] = 0;
    float s = 0.f;
    for (int c = lane; c < C_; c += 32) { float v = sim[(size_t)c*E_ + e]; s += v*v; }
    #pragma unroll
    for (int o = 16; o > 0; o >>= 1) s += __shfl_xor_sync(0xffffffffu, s, o);
    if (lane == 0) {
        g_invsn[e] = 1.0f / fmaxf(sqrtf(s), 1e-12f);
        g_sig[e]   = 1.0f / (1.0f + expf(-gates[e]));
    }
}

// ---------------- gating (one warp per token) ------------------------------------
__global__ void gating_kernel(const float* __restrict__ x, const float* __restrict__ sim) {
    int tok  = blockIdx.x * (blockDim.x >> 5) + (threadIdx.x >> 5);
    int lane = threadIdx.x & 31;
    if (tok >= N_) return;
    const float* xr = x + (size_t)tok * C_;

    float dot[E_];
    #pragma unroll
    for (int e = 0; e < E_; e++) dot[e] = 0.f;
    float nrm = 0.f;
    for (int c = lane; c < C_; c += 32) {
        float xv = xr[c];
        nrm += xv * xv;
        const float4* s4 = (const float4*)(sim + (size_t)c * E_);
        float4 r0 = s4[0], r1 = s4[1], r2 = s4[2], r3 = s4[3];
        dot[0]+=xv*r0.x; dot[1]+=xv*r0.y; dot[2]+=xv*r0.z; dot[3]+=xv*r0.w;
        dot[4]+=xv*r1.x; dot[5]+=xv*r1.y; dot[6]+=xv*r1.z; dot[7]+=xv*r1.w;
        dot[8]+=xv*r2.x; dot[9]+=xv*r2.y; dot[10]+=xv*r2.z; dot[11]+=xv*r2.w;
        dot[12]+=xv*r3.x; dot[13]+=xv*r3.y; dot[14]+=xv*r3.z; dot[15]+=xv*r3.w;
    }
    #pragma unroll
    for (int o = 16; o > 0; o >>= 1) {
        nrm += __shfl_xor_sync(0xffffffffu, nrm, o);
        #pragma unroll
        for (int e = 0; e < E_; e++) dot[e] += __shfl_xor_sync(0xffffffffu, dot[e], o);
    }
    float invx = 1.0f / fmaxf(sqrtf(nrm), 1e-12f);

    float logit[E_], gated[E_];
    unsigned msk = 0u;
    #pragma unroll
    for (int e = 0; e < E_; e++) {
        logit[e] = dot[e] * invx * g_invsn[e] - g_sig[e];
        gated[e] = fmaxf(logit[e], 0.f);
        if (logit[e] > 0.f) msk |= (1u << e);
    }
    if (msk == 0u) {
        float m1 = -3.4e38f; int i1 = 0;
        #pragma unroll
        for (int e = 0; e < E_; e++) if (logit[e] > m1) { m1 = logit[e]; i1 = e; }
        float m2 = -3.4e38f; int i2 = 0;
        #pragma unroll
        for (int e = 0; e < E_; e++) if (e != i1 && logit[e] > m2) { m2 = logit[e]; i2 = e; }
        msk = (1u << i1) | (1u << i2);
    }
    float mx = -3.4e38f;
    #pragma unroll
    for (int e = 0; e < E_; e++) if ((msk >> e) & 1u) mx = fmaxf(mx, gated[e]);
    float wv[E_]; float sum = 0.f;
    #pragma unroll
    for (int e = 0; e < E_; e++) {
        wv[e] = ((msk >> e) & 1u) ? expf(gated[e] - mx) : 0.f;
        sum += wv[e];
    }
    float inv = 1.0f / sum;
    #pragma unroll
    for (int e = 0; e < E_; e++) {
        if (lane == e && ((msk >> e) & 1u)) {
            int pos = atomicAdd(&g_cnt[e], 1);
            g_idx[(size_t)e * N_ + pos] = tok;
            g_wt [(size_t)e * N_ + pos] = wv[e] * inv;
        }
    }
}

// ---------------- fused operand prep ---------------------------------------------
__global__ void prep_operands(const float* __restrict__ qp, const float* __restrict__ kp,
                              const float* __restrict__ vp, const float* __restrict__ op,
                              const float* __restrict__ x,  float* __restrict__ out)
{
    int z = blockIdx.z;
    int tid = threadIdx.x;
    if (z < 64) {
        __shared__ float tsm[32][33];
        int e = z >> 2, mat = z & 3;
        const float* in;
        half* oh;
        int R, Cc, c0, r0;
        if (mat == 0)      { in = qp; oh = g_wqh; }
        else if (mat == 1) { in = kp; oh = g_wkh; }
        else if (mat == 2) { in = vp; oh = g_wvh; }
        else               { in = op; oh = g_woh; }
        if (mat < 3) { R = C_; Cc = H_; c0 = blockIdx.x * 32; r0 = blockIdx.y * 32; }
        else         { R = H_; Cc = C_; c0 = blockIdx.y * 32; r0 = blockIdx.x * 32; }
        size_t zo = (size_t)e * R * Cc;
        in += zo; oh += zo;
        int tx = tid & 31, ty = tid >> 5;
        #pragma unroll
        for (int i = ty; i < 32; i += 8) tsm[i][tx] = in[(size_t)(r0 + i) * Cc + c0 + tx];
        __syncthreads();
        #pragma unroll
        for (int i = ty; i < 32; i += 8)
            oh[(size_t)(c0 + i) * R + r0 + tx] = __float2half_rn(tsm[tx][i]);
    } else {
        long flat = (long)(z - 64) * 128 + blockIdx.y * 4 + blockIdx.x;  // 0..4095
        const long STRIDE = 2048L * 256;
        if (flat < 2048) {
            long i = flat * 256 + tid;
            long n4 = (long)N_ * C_ / 4;
            for (; i < n4; i += STRIDE) {
                float4 v = ((const float4*)x)[i];
                half h0, l0, h1, l1, h2, l2, h3, l3;
                split_f32(v.x, h0, l0); split_f32(v.y, h1, l1);
                split_f32(v.z, h2, l2); split_f32(v.w, h3, l3);
                ((__half2*)g_xh)[2*i]   = __halves2half2(h0, h1);
                ((__half2*)g_xh)[2*i+1] = __halves2half2(h2, h3);
                ((__half2*)g_xl)[2*i]   = __halves2half2(l0, l1);
                ((__half2*)g_xl)[2*i+1] = __halves2half2(l2, l3);
            }
        } else {
            long i = (flat - 2048) * 256 + tid;
            float4 zf = make_float4(0.f, 0.f, 0.f, 0.f);
            long nqkv = (long)N_ * H_ / 4;
            for (long j = i; j < nqkv; j += STRIDE) {
                ((float4*)g_q)[j] = zf; ((float4*)g_k)[j] = zf;
                ((float4*)g_v)[j] = zf; ((float4*)g_o)[j] = zf;
            }
            long nout = (long)N_ * C_ / 4;
            for (long j = i; j < nout; j += STRIDE) ((float4*)out)[j] = zf;
        }
    }
}

// ---------------- split q (hi/lo) + convert k (hi) -------------------------------
__global__ void split_qk() {
    long i  = (long)blockIdx.x * blockDim.x + threadIdx.x;
    long st = (long)gridDim.x * blockDim.x;
    long n4 = (long)N_ * H_ / 4;
    for (; i < n4; i += st) {
        float4 qv = ((const float4*)g_q)[i];
        half h0, l0, h1, l1, h2, l2, h3, l3;
        split_f32(qv.x, h0, l0); split_f32(qv.y, h1, l1);
        split_f32(qv.z, h2, l2); split_f32(qv.w, h3, l3);
        ((__half2*)g_qh)[2*i]   = __halves2half2(h0, h1);
        ((__half2*)g_qh)[2*i+1] = __halves2half2(h2, h3);
        ((__half2*)g_ql)[2*i]   = __halves2half2(l0, l1);
        ((__half2*)g_ql)[2*i+1] = __halves2half2(l2, l3);
        float4 kv = ((const float4*)g_k)[i];
        ((__half2*)g_kh)[2*i]   = __halves2half2(__float2half_rn(kv.x), __float2half_rn(kv.y));
        ((__half2*)g_kh)[2*i+1] = __halves2half2(__float2half_rn(kv.z), __float2half_rn(kv.w));
    }
}

// ---------------- split o (hi/lo) ------------------------------------------------
__global__ void split_o() {
    long i  = (long)blockIdx.x * blockDim.x + threadIdx.x;
    long st = (long)gridDim.x * blockDim.x;
    long n4 = (long)N_ * H_ / 4;
    for (; i < n4; i += st) {
        float4 v = ((const float4*)g_o)[i];
        half h0, l0, h1, l1, h2, l2, h3, l3;
        split_f32(v.x, h0, l0); split_f32(v.y, h1, l1);
        split_f32(v.z, h2, l2); split_f32(v.w, h3, l3);
        ((__half2*)g_oh)[2*i]   = __halves2half2(h0, h1);
        ((__half2*)g_oh)[2*i+1] = __halves2half2(h2, h3);
        ((__half2*)g_ol)[2*i]   = __halves2half2(l0, l1);
        ((__half2*)g_ol)[2*i+1] = __halves2half2(l2, l3);
    }
}

// ---------------- transpose v -> vT (fp16 hi only), per batch --------------------
__global__ void tsplit_h() {
    __shared__ float tsm[32][33];
    size_t zo = (size_t)blockIdx.z * T_ * H_;
    const float* in = g_v + zo;
    half* oh = g_vTh + zo;
    int c0 = blockIdx.x * 32, r0 = blockIdx.y * 32;
    int tx = threadIdx.x, ty = threadIdx.y;
    #pragma unroll
    for (int i = ty; i < 32; i += 8) tsm[i][tx] = in[(size_t)(r0 + i) * H_ + c0 + tx];
    __syncthreads();
    #pragma unroll
    for (int i = ty; i < 32; i += 8)
        oh[(size_t)(c0 + i) * T_ + r0 + tx] = __float2half_rn(tsm[tx][i]);
}

// ---------------- softmax over S rows, writing fp16 hi/lo (vectorized) -----------
__global__ void softmax_split() {
    __shared__ float buf[T_];
    __shared__ float red[8];
    const float4* S4 = (const float4*)(g_S + (size_t)blockIdx.x * T_);
    __half2* sh = (__half2*)(g_Sh + (size_t)blockIdx.x * T_);
    __half2* sl = (__half2*)(g_Sl + (size_t)blockIdx.x * T_);
    int tid = threadIdx.x, lane = tid & 31, wrp = tid >> 5;

    float mx = -3.4e38f;
    #pragma unroll
    for (int it = 0; it < 2; it++) {
        int j = tid + it * 256;
        float4 v = S4[j];
        ((float4*)buf)[j] = v;
        mx = fmaxf(mx, fmaxf(fmaxf(v.x, v.y), fmaxf(v.z, v.w)));
    }
    #pragma unroll
    for (int o = 16; o > 0; o >>= 1) mx = fmaxf(mx, __shfl_xor_sync(0xffffffffu, mx, o));
    if (lane == 0) red[wrp] = mx;
    __syncthreads();
    mx = red[lane & 7];
    #pragma unroll
    for (int o = 4; o > 0; o >>= 1) mx = fmaxf(mx, __shfl_xor_sync(0xffffffffu, mx, o));

    float sum = 0.f;
    #pragma unroll
    for (int it = 0; it < 2; it++) {
        int j = tid + it * 256;
        float4 v = ((float4*)buf)[j];
        v.x = __expf(v.x - mx); v.y = __expf(v.y - mx);
        v.z = __expf(v.z - mx); v.w = __expf(v.w - mx);
        ((float4*)buf)[j] = v;
        sum += v.x + v.y + v.z + v.w;
    }
    #pragma unroll
    for (int o = 16; o > 0; o >>= 1) sum += __shfl_xor_sync(0xffffffffu, sum, o);
    __syncthreads();
    if (lane == 0) red[wrp] = sum;
    __syncthreads();
    sum = red[lane & 7];
    #pragma unroll
    for (int o = 4; o > 0; o >>= 1) sum += __shfl_xor_sync(0xffffffffu, sum, o);
    float inv = 1.0f / sum;

    #pragma unroll
    for (int it = 0; it < 2; it++) {
        int j = tid + it * 256;
        float4 v = ((float4*)buf)[j];
        half h0, l0, h1, l1, h2, l2, h3, l3;
        split_f32(v.x * inv, h0, l0); split_f32(v.y * inv, h1, l1);
        split_f32(v.z * inv, h2, l2); split_f32(v.w * inv, h3, l3);
        sh[2*j]   = __halves2half2(h0, h1);
        sh[2*j+1] = __halves2half2(h2, h3);
        sl[2*j]   = __halves2half2(l0, l1);
        sl[2*j+1] = __halves2half2(l2, l3);
    }
}

// ---------------- launch ---------------------------------------------------------
extern "C" void kernel_launch(void* const* d_in, const int* in_sizes, int n_in,
                              void* d_out, int out_size)
{
    const float* x     = (const float*)d_in[0];
    const float* sim   = (const float*)d_in[1];
    const float* gates = (const float*)d_in[2];
    const float* qp    = (const float*)d_in[3];
    const float* kp    = (const float*)d_in[4];
    const float* vp    = (const float*)d_in[5];
    const float* op    = (const float*)d_in[6];
    float* outp = (float*)d_out;

    float *q, *k, *v, *o, *S, *wt;
    int *cnt, *idx;
    half *xh, *xl, *qh, *ql, *kh, *vTh, *oh, *ol, *Sh, *Sl;
    half *wqh, *wkh, *wvh, *woh;
    cudaGetSymbolAddress((void**)&q, g_q);     cudaGetSymbolAddress((void**)&k, g_k);
    cudaGetSymbolAddress((void**)&v, g_v);     cudaGetSymbolAddress((void**)&o, g_o);
    cudaGetSymbolAddress((void**)&S, g_S);
    cudaGetSymbolAddress((void**)&cnt, g_cnt); cudaGetSymbolAddress((void**)&idx, g_idx);
    cudaGetSymbolAddress((void**)&wt, g_wt);
    cudaGetSymbolAddress((void**)&xh, g_xh);   cudaGetSymbolAddress((void**)&xl, g_xl);
    cudaGetSymbolAddress((void**)&qh, g_qh);   cudaGetSymbolAddress((void**)&ql, g_ql);
    cudaGetSymbolAddress((void**)&kh, g_kh);
    cudaGetSymbolAddress((void**)&vTh, g_vTh);
    cudaGetSymbolAddress((void**)&oh, g_oh);   cudaGetSymbolAddress((void**)&ol, g_ol);
    cudaGetSymbolAddress((void**)&Sh, g_Sh);   cudaGetSymbolAddress((void**)&Sl, g_Sl);
    cudaGetSymbolAddress((void**)&wqh, g_wqh); cudaGetSymbolAddress((void**)&wkh, g_wkh);
    cudaGetSymbolAddress((void**)&wvh, g_wvh); cudaGetSymbolAddress((void**)&woh, g_woh);

    cudaFuncSetAttribute(hm_gemm<true,  true >, cudaFuncAttributeMaxDynamicSharedMemorySize, DSM_BYTES);
    cudaFuncSetAttribute(hm_gemm<false, false>, cudaFuncAttributeMaxDynamicSharedMemorySize, DSM_BYTES);
    cudaFuncSetAttribute(hm_gemm<false, true >, cudaFuncAttributeMaxDynamicSharedMemorySize, DSM_BYTES);

    prep_kernel<<<1, 512>>>(sim, gates);                               // 1
    gating_kernel<<<N_/8, 256>>>(x, sim);                              // 2
    prep_operands<<<dim3(4, 32, 96), 256>>>(qp, kp, vp, op, x, outp);  // 3

    // 4: QKV MoE dispatch (gathered, weighted atomic accumulate, split-K x2)
    {
        TCArgs a{};
        a.Ah = xh; a.Al = xl;
        a.Bh0 = wqh; a.Bh1 = wkh; a.Bh2 = wvh;
        a.C0 = q; a.C1 = k; a.C2 = v;
        a.sAz = 0; a.sBz = (long)H_*C_; a.sCz = 0;
        a.lda = C_; a.ldb = C_; a.ldc = H_;
        a.M = N_; a.K = C_; a.nxb = 2; a.nsplit = 2; a.ksplit = 512;
        a.alpha = 1.f; a.cnt = cnt; a.idxB = idx; a.wtB = wt;
        hm_gemm<true, true><<<dim3(6, 64, 32), 256, DSM_BYTES>>>(a);
    }

    split_qk<<<512, 256>>>();                                          // 5
    tsplit_h<<<dim3(H_/32, T_/32, B_), dim3(32,8)>>>();                // 6

    // 7: S = Q K^T / sqrt(H)
    {
        TCArgs a{};
        a.Ah = qh; a.Al = ql;
        a.Bh0 = kh; a.Bh1 = kh; a.Bh2 = kh;
        a.C0 = S; a.C1 = S; a.C2 = S;
        a.sAz = (long)T_*H_; a.sBz = (long)T_*H_; a.sCz = (long)T_*T_;
        a.lda = H_; a.ldb = H_; a.ldc = T_;
        a.M = T_; a.K = H_; a.nxb = 32; a.nsplit = 1; a.ksplit = H_;
        a.alpha = 0.08838834764831845f;
        hm_gemm<false, false><<<dim3(32, 16, 4), 256, DSM_BYTES>>>(a);
    }

    softmax_split<<<B_*T_, 256>>>();                                   // 8

    // 9: O = P V   (split-K x8, atomic accumulate into o f32)
    {
        TCArgs a{};
        a.Ah = Sh; a.Al = Sl;
        a.Bh0 = vTh; a.Bh1 = vTh; a.Bh2 = vTh;
        a.C0 = o; a.C1 = o; a.C2 = o;
        a.sAz = (long)T_*T_; a.sBz = (long)H_*T_; a.sCz = (long)T_*H_;
        a.lda = T_; a.ldb = T_; a.ldc = H_;
        a.M = T_; a.K = T_; a.nxb = 2; a.nsplit = 8; a.ksplit = 256;
        a.alpha = 1.f;
        hm_gemm<false, true><<<dim3(2, 16, 32), 256, DSM_BYTES>>>(a);
    }

    split_o<<<512, 256>>>();                                           // 10

    // 11: output MoE combine (gathered, weighted atomic accumulate into out)
    {
        TCArgs a{};
        a.Ah = oh; a.Al = ol;
        a.Bh0 = woh; a.Bh1 = woh; a.Bh2 = woh;
        a.C0 = outp; a.C1 = outp; a.C2 = outp;
        a.sAz = 0; a.sBz = (long)C_*H_; a.sCz = 0;
        a.lda = H_; a.ldb = H_; a.ldc = C_;
        a.M = N_; a.K = H_; a.nxb = 16; a.nsplit = 1; a.ksplit = H_;
        a.alpha = 1.f; a.cnt = cnt; a.idxB = idx; a.wtB = wt;
        hm_gemm<true, true><<<dim3(16, 64, 16), 256, DSM_BYTES>>>(a);
    }
}

// round 15
// speedup vs baseline: 1.1429x; 1.1429x over previous
#include <cuda_runtime.h>
#include <cuda_fp16.h>
#include <math.h>
#include <stdint.h>

#define B_ 4
#define T_ 2048
#define C_ 1024
#define H_ 128
#define E_ 16
#define N_ (B_*T_)   /* 8192 tokens */

// ---------------- scratch (allocation-free: __device__ globals) ----------------
__device__ float g_q[(size_t)N_*H_];
__device__ float g_k[(size_t)N_*H_];
__device__ float g_v[(size_t)N_*H_];
__device__ float g_o[(size_t)N_*H_];
__device__ float g_S[(size_t)B_*T_*T_];          // 64 MB f32 scores

__device__ half g_xh[(size_t)N_*C_],  g_xl[(size_t)N_*C_];
__device__ half g_qh[(size_t)N_*H_],  g_ql[(size_t)N_*H_];
__device__ half g_kh[(size_t)N_*H_];
__device__ half g_vTh[(size_t)N_*H_];                         // [B][H][T]
__device__ half g_oh[(size_t)N_*H_],  g_ol[(size_t)N_*H_];
__device__ half g_Sh[(size_t)B_*T_*T_];
__device__ half g_wqh[(size_t)E_*H_*C_];                      // [E][H][C]
__device__ half g_wkh[(size_t)E_*H_*C_];
__device__ half g_wvh[(size_t)E_*H_*C_];
__device__ half g_woh[(size_t)E_*C_*H_];                      // [E][C][H]

__device__ int   g_cnt[E_];
__device__ int   g_idx[(size_t)E_*N_];
__device__ float g_wt[(size_t)E_*N_];
__device__ float g_invsn[E_];
__device__ float g_sig[E_];

// ---------------- mma.sync / ldmatrix / cp.async helpers (baseline PTX) ---------
#define MMA16816(d, A0, A1, A2, A3, Bv0, Bv1) \
    asm volatile("mma.sync.aligned.m16n8k16.row.col.f32.f16.f16.f32 " \
        "{%0,%1,%2,%3},{%4,%5,%6,%7},{%8,%9},{%0,%1,%2,%3};" \
        : "+f"((d)[0]), "+f"((d)[1]), "+f"((d)[2]), "+f"((d)[3]) \
        : "r"(A0), "r"(A1), "r"(A2), "r"(A3), "r"(Bv0), "r"(Bv1))

#define LDSM4(r0, r1, r2, r3, addr) \
    asm volatile("ldmatrix.sync.aligned.m8n8.x4.shared.b16 {%0,%1,%2,%3}, [%4];" \
        : "=r"(r0), "=r"(r1), "=r"(r2), "=r"(r3) : "r"(addr))

#define CPA16(dst, src) \
    asm volatile("cp.async.cg.shared.global [%0], [%1], 16;" :: "r"(dst), "l"(src))

__device__ __forceinline__ uint32_t smem_u32(const void* p) {
    uint32_t a;
    asm("{ .reg .u64 t; cvta.to.shared.u64 t, %1; cvt.u32.u64 %0, t; }" : "=r"(a) : "l"(p));
    return a;
}

__device__ __forceinline__ void split_f32(float v, half& h, half& l) {
    h = __float2half_rn(v);
    l = __float2half_rn(v - __half2float(h));
}

// ---------------- HMMA GEMM -------------------------------------------------------
// TWOTERM: D = (Ah+Al) * Bh ; else D = Ah * Bh
// CTA tile 128x128, k-chunk 32, warp grid 2m x 4n (R13 shape)
struct TCArgs {
    const half *Ah, *Al;
    const half *Bh0, *Bh1, *Bh2;
    float *C0, *C1, *C2;
    long sAz, sBz, sCz;
    int  lda, ldb, ldc;
    int  M, K, nxb, nsplit, ksplit;
    float alpha;
    const int* cnt; const int* idxB; const float* wtB;
};

#define PITCH 20   /* row pitch in b32 units: 16 b32 (32 fp16) + 4 pad */
#define TILE_U32 (128*PITCH)
#define DSM_BYTES (3*3*TILE_U32*4)   /* 3 stages x 3 tiles = 92160 B */

template<bool GATHER, bool ATOMIC, bool TWOTERM>
__global__ void __launch_bounds__(256, 2) hm_gemm(TCArgs a)
{
    int zb  = blockIdx.z / a.nsplit;
    int sp  = blockIdx.z % a.nsplit;
    int mat = blockIdx.x / a.nxb;
    int n0  = (blockIdx.x % a.nxb) * 128;

    int Mz = a.M;
    const int*   gidx = nullptr;
    const float* gwt  = nullptr;
    if (GATHER) {
        Mz   = a.cnt[zb];
        gidx = a.idxB + (size_t)zb * N_;
        gwt  = a.wtB  + (size_t)zb * N_;
    }
    int m0 = blockIdx.y * 128;
    if (m0 >= Mz) return;

    const half* Ah = a.Ah + (size_t)zb * a.sAz;
    const half* Al = a.Al + (size_t)zb * a.sAz;
    const half* Bh = (mat == 0 ? a.Bh0 : mat == 1 ? a.Bh1 : a.Bh2) + (size_t)zb * a.sBz;
    float*      C  = (mat == 0 ? a.C0  : mat == 1 ? a.C1  : a.C2)  + (size_t)zb * a.sCz;

    extern __shared__ uint32_t dsm[];
    uint32_t smbase = smem_u32(dsm);

    __shared__ int   s_idx[128];
    __shared__ float s_wt[128];

    int tid  = threadIdx.x;
    int lane = tid & 31, wid = tid >> 5;
    int g = lane >> 2, t = lane & 3;
    int wm = wid & 1, wn = wid >> 1;          // warp grid 2 (m) x 4 (n)
    int mbw = wm * 64, nbw = wn * 32;

    if (GATHER) {
        for (int i = tid; i < 128; i += 256) {
            int r = m0 + i;
            bool v = r < Mz;
            s_idx[i] = v ? gidx[r] : 0;
            s_wt[i]  = v ? gwt[r] : 0.f;
        }
    }
    __syncthreads();

    float acc[4][4][4];
    #pragma unroll
    for (int i = 0; i < 4; i++)
        #pragma unroll
        for (int j = 0; j < 4; j++)
            #pragma unroll
            for (int c = 0; c < 4; c++) acc[i][j][c] = 0.f;

    int kb = sp * a.ksplit;
    int ke = kb + a.ksplit; if (ke > a.K) ke = a.K;
    int nch = (ke - kb) >> 5;

    // per-thread global load coordinates (fixed across k-chunks)
    int f0row = tid >> 2,          f0kq = tid & 3;
    int f1row = (tid + 256) >> 2,  f1kq = (tid + 256) & 3;
    long ar0 = GATHER ? (long)s_idx[f0row] : (long)(m0 + f0row);
    long ar1 = GATHER ? (long)s_idx[f1row] : (long)(m0 + f1row);
    long br0 = (long)(n0 + f0row), br1 = (long)(n0 + f1row);
    uint32_t so0 = (uint32_t)(f0row * PITCH + f0kq * 4) * 4u;
    uint32_t so1 = (uint32_t)(f1row * PITCH + f1kq * 4) * 4u;

    // ldmatrix lane-address offsets (bytes)
    int jj = lane >> 3, rr = lane & 7;
    uint32_t aoff = (uint32_t)(((jj & 1) * 8 + rr) * PITCH + (jj >> 1) * 4) * 4u;
    uint32_t boff = (uint32_t)(((jj >> 1) * 8 + rr) * PITCH + (jj & 1) * 4) * 4u;
    uint32_t baseA = smbase + (uint32_t)(mbw * PITCH) * 4u + aoff;
    uint32_t baseB = smbase + (uint32_t)(nbw * PITCH) * 4u + boff;
    const uint32_t TB = (uint32_t)TILE_U32 * 4u;   // tile stride in bytes

    // chunk loader into stage s (tiles: Ah, [Al], Bh)
    auto load_chunk = [&](int k0, int s) {
        uint32_t bb = (uint32_t)(s * 3) * TB;
        CPA16(smbase + bb + 0*TB + so0, Ah + ar0 * (long)a.lda + k0 + f0kq * 8);
        CPA16(smbase + bb + 0*TB + so1, Ah + ar1 * (long)a.lda + k0 + f1kq * 8);
        if (TWOTERM) {
            CPA16(smbase + bb + 1*TB + so0, Al + ar0 * (long)a.lda + k0 + f0kq * 8);
            CPA16(smbase + bb + 1*TB + so1, Al + ar1 * (long)a.lda + k0 + f1kq * 8);
        }
        CPA16(smbase + bb + 2*TB + so0, Bh + br0 * (long)a.ldb + k0 + f0kq * 8);
        CPA16(smbase + bb + 2*TB + so1, Bh + br1 * (long)a.ldb + k0 + f1kq * 8);
    };

    // 3-stage pipeline prologue
    load_chunk(kb, 0);
    asm volatile("cp.async.commit_group;" ::: "memory");
    if (nch > 1) {
        load_chunk(kb + 32, 1);
        asm volatile("cp.async.commit_group;" ::: "memory");
    }

    int stage = 0;
    for (int i = 0; i < nch; i++) {
        if (i < nch - 1) asm volatile("cp.async.wait_group 1;" ::: "memory");
        else             asm volatile("cp.async.wait_group 0;" ::: "memory");
        __syncthreads();

        if (i + 2 < nch) {
            int s2 = stage + 2; if (s2 >= 3) s2 -= 3;
            load_chunk(kb + (i + 2) * 32, s2);
            asm volatile("cp.async.commit_group;" ::: "memory");
        }

        uint32_t bb = (uint32_t)(stage * 3) * TB;
        uint32_t bAh = baseA + bb + 0*TB, bAl = baseA + bb + 1*TB;
        uint32_t bBh = baseB + bb + 2*TB;

        #pragma unroll
        for (int kk = 0; kk < 2; kk++) {
            uint32_t kadd = (uint32_t)(kk * 8) * 4u;
            uint32_t bh[4][2];
            #pragma unroll
            for (int np = 0; np < 2; np++) {
                uint32_t ba = (uint32_t)(np * 16 * PITCH) * 4u + kadd;
                LDSM4(bh[2*np][0], bh[2*np][1], bh[2*np+1][0], bh[2*np+1][1], bBh + ba);
            }
            #pragma unroll
            for (int mt = 0; mt < 4; mt++) {
                uint32_t ma = (uint32_t)(mt * 16 * PITCH) * 4u + kadd;
                uint32_t ah0, ah1, ah2, ah3;
                LDSM4(ah0, ah1, ah2, ah3, bAh + ma);
                if (TWOTERM) {
                    uint32_t al0, al1, al2, al3;
                    LDSM4(al0, al1, al2, al3, bAl + ma);
                    #pragma unroll
                    for (int nt = 0; nt < 4; nt++) {
                        MMA16816(acc[mt][nt], ah0, ah1, ah2, ah3, bh[nt][0], bh[nt][1]);
                        MMA16816(acc[mt][nt], al0, al1, al2, al3, bh[nt][0], bh[nt][1]);
                    }
                } else {
                    #pragma unroll
                    for (int nt = 0; nt < 4; nt++)
                        MMA16816(acc[mt][nt], ah0, ah1, ah2, ah3, bh[nt][0], bh[nt][1]);
                }
            }
        }
        stage = stage + 1; if (stage >= 3) stage -= 3;
    }

    // epilogue: c0,c1 -> row (g), cols 2t,2t+1 ; c2,c3 -> row (g+8)
    #pragma unroll
    for (int mt = 0; mt < 4; mt++) {
        #pragma unroll
        for (int half_ = 0; half_ < 2; half_++) {
            int lr = mbw + mt * 16 + g + half_ * 8;
            bool rv; long orow; float sc;
            if (GATHER) { rv = (m0 + lr) < Mz; orow = s_idx[lr]; sc = a.alpha * s_wt[lr]; }
            else        { rv = true;           orow = m0 + lr;   sc = a.alpha; }
            if (rv) {
                float* cp = C + orow * (long)a.ldc + n0 + nbw;
                #pragma unroll
                for (int nt = 0; nt < 4; nt++) {
                    int col = nt * 8 + 2 * t;
                    float v0 = acc[mt][nt][half_ * 2 + 0] * sc;
                    float v1 = acc[mt][nt][half_ * 2 + 1] * sc;
                    if (ATOMIC) { atomicAdd(cp + col, v0); atomicAdd(cp + col + 1, v1); }
                    else        { float2 vv; vv.x = v0; vv.y = v1; *(float2*)(cp + col) = vv; }
                }
            }
        }
    }
}

// ---------------- sim-matrix column norms + sigmoid(gates) + counter reset -------
__global__ void prep_kernel(const float* __restrict__ sim, const float* __restrict__ gates) {
    int e = threadIdx.x >> 5, lane = threadIdx.x & 31;
    if (threadIdx.x < E_) g_cnt[threadIdx.x] = 0;
    float s = 0.f;
    for (int c = lane; c < C_; c += 32) { float v = sim[(size_t)c*E_ + e]; s += v*v; }
    #pragma unroll
    for (int o = 16; o > 0; o >>= 1) s += __shfl_xor_sync(0xffffffffu, s, o);
    if (lane == 0) {
        g_invsn[e] = 1.0f / fmaxf(sqrtf(s), 1e-12f);
        g_sig[e]   = 1.0f / (1.0f + expf(-gates[e]));
    }
}

// ---------------- gating (one warp per token) ------------------------------------
__global__ void gating_kernel(const float* __restrict__ x, const float* __restrict__ sim) {
    int tok  = blockIdx.x * (blockDim.x >> 5) + (threadIdx.x >> 5);
    int lane = threadIdx.x & 31;
    if (tok >= N_) return;
    const float* xr = x + (size_t)tok * C_;

    float dot[E_];
    #pragma unroll
    for (int e = 0; e < E_; e++) dot[e] = 0.f;
    float nrm = 0.f;
    for (int c = lane; c < C_; c += 32) {
        float xv = xr[c];
        nrm += xv * xv;
        const float4* s4 = (const float4*)(sim + (size_t)c * E_);
        float4 r0 = s4[0], r1 = s4[1], r2 = s4[2], r3 = s4[3];
        dot[0]+=xv*r0.x; dot[1]+=xv*r0.y; dot[2]+=xv*r0.z; dot[3]+=xv*r0.w;
        dot[4]+=xv*r1.x; dot[5]+=xv*r1.y; dot[6]+=xv*r1.z; dot[7]+=xv*r1.w;
        dot[8]+=xv*r2.x; dot[9]+=xv*r2.y; dot[10]+=xv*r2.z; dot[11]+=xv*r2.w;
        dot[12]+=xv*r3.x; dot[13]+=xv*r3.y; dot[14]+=xv*r3.z; dot[15]+=xv*r3.w;
    }
    #pragma unroll
    for (int o = 16; o > 0; o >>= 1) {
        nrm += __shfl_xor_sync(0xffffffffu, nrm, o);
        #pragma unroll
        for (int e = 0; e < E_; e++) dot[e] += __shfl_xor_sync(0xffffffffu, dot[e], o);
    }
    float invx = 1.0f / fmaxf(sqrtf(nrm), 1e-12f);

    float logit[E_], gated[E_];
    unsigned msk = 0u;
    #pragma unroll
    for (int e = 0; e < E_; e++) {
        logit[e] = dot[e] * invx * g_invsn[e] - g_sig[e];
        gated[e] = fmaxf(logit[e], 0.f);
        if (logit[e] > 0.f) msk |= (1u << e);
    }
    if (msk == 0u) {
        float m1 = -3.4e38f; int i1 = 0;
        #pragma unroll
        for (int e = 0; e < E_; e++) if (logit[e] > m1) { m1 = logit[e]; i1 = e; }
        float m2 = -3.4e38f; int i2 = 0;
        #pragma unroll
        for (int e = 0; e < E_; e++) if (e != i1 && logit[e] > m2) { m2 = logit[e]; i2 = e; }
        msk = (1u << i1) | (1u << i2);
    }
    float mx = -3.4e38f;
    #pragma unroll
    for (int e = 0; e < E_; e++) if ((msk >> e) & 1u) mx = fmaxf(mx, gated[e]);
    float wv[E_]; float sum = 0.f;
    #pragma unroll
    for (int e = 0; e < E_; e++) {
        wv[e] = ((msk >> e) & 1u) ? expf(gated[e] - mx) : 0.f;
        sum += wv[e];
    }
    float inv = 1.0f / sum;
    #pragma unroll
    for (int e = 0; e < E_; e++) {
        if (lane == e && ((msk >> e) & 1u)) {
            int pos = atomicAdd(&g_cnt[e], 1);
            g_idx[(size_t)e * N_ + pos] = tok;
            g_wt [(size_t)e * N_ + pos] = wv[e] * inv;
        }
    }
}

// ---------------- fused operand prep ---------------------------------------------
__global__ void prep_operands(const float* __restrict__ qp, const float* __restrict__ kp,
                              const float* __restrict__ vp, const float* __restrict__ op,
                              const float* __restrict__ x,  float* __restrict__ out)
{
    int z = blockIdx.z;
    int tid = threadIdx.x;
    if (z < 64) {
        __shared__ float tsm[32][33];
        int e = z >> 2, mat = z & 3;
        const float* in;
        half* oh;
        int R, Cc, c0, r0;
        if (mat == 0)      { in = qp; oh = g_wqh; }
        else if (mat == 1) { in = kp; oh = g_wkh; }
        else if (mat == 2) { in = vp; oh = g_wvh; }
        else               { in = op; oh = g_woh; }
        if (mat < 3) { R = C_; Cc = H_; c0 = blockIdx.x * 32; r0 = blockIdx.y * 32; }
        else         { R = H_; Cc = C_; c0 = blockIdx.y * 32; r0 = blockIdx.x * 32; }
        size_t zo = (size_t)e * R * Cc;
        in += zo; oh += zo;
        int tx = tid & 31, ty = tid >> 5;
        #pragma unroll
        for (int i = ty; i < 32; i += 8) tsm[i][tx] = in[(size_t)(r0 + i) * Cc + c0 + tx];
        __syncthreads();
        #pragma unroll
        for (int i = ty; i < 32; i += 8)
            oh[(size_t)(c0 + i) * R + r0 + tx] = __float2half_rn(tsm[tx][i]);
    } else {
        long flat = (long)(z - 64) * 128 + blockIdx.y * 4 + blockIdx.x;  // 0..4095
        const long STRIDE = 2048L * 256;
        if (flat < 2048) {
            long i = flat * 256 + tid;
            long n4 = (long)N_ * C_ / 4;
            for (; i < n4; i += STRIDE) {
                float4 v = ((const float4*)x)[i];
                half h0, l0, h1, l1, h2, l2, h3, l3;
                split_f32(v.x, h0, l0); split_f32(v.y, h1, l1);
                split_f32(v.z, h2, l2); split_f32(v.w, h3, l3);
                ((__half2*)g_xh)[2*i]   = __halves2half2(h0, h1);
                ((__half2*)g_xh)[2*i+1] = __halves2half2(h2, h3);
                ((__half2*)g_xl)[2*i]   = __halves2half2(l0, l1);
                ((__half2*)g_xl)[2*i+1] = __halves2half2(l2, l3);
            }
        } else {
            long i = (flat - 2048) * 256 + tid;
            float4 zf = make_float4(0.f, 0.f, 0.f, 0.f);
            long nqkv = (long)N_ * H_ / 4;
            for (long j = i; j < nqkv; j += STRIDE) {
                ((float4*)g_q)[j] = zf; ((float4*)g_k)[j] = zf;
                ((float4*)g_v)[j] = zf; ((float4*)g_o)[j] = zf;
            }
            long nout = (long)N_ * C_ / 4;
            for (long j = i; j < nout; j += STRIDE) ((float4*)out)[j] = zf;
        }
    }
}

// ---------------- split q (hi/lo) + convert k (hi) -------------------------------
__global__ void split_qk() {
    long i  = (long)blockIdx.x * blockDim.x + threadIdx.x;
    long st = (long)gridDim.x * blockDim.x;
    long n4 = (long)N_ * H_ / 4;
    for (; i < n4; i += st) {
        float4 qv = ((const float4*)g_q)[i];
        half h0, l0, h1, l1, h2, l2, h3, l3;
        split_f32(qv.x, h0, l0); split_f32(qv.y, h1, l1);
        split_f32(qv.z, h2, l2); split_f32(qv.w, h3, l3);
        ((__half2*)g_qh)[2*i]   = __halves2half2(h0, h1);
        ((__half2*)g_qh)[2*i+1] = __halves2half2(h2, h3);
        ((__half2*)g_ql)[2*i]   = __halves2half2(l0, l1);
        ((__half2*)g_ql)[2*i+1] = __halves2half2(l2, l3);
        float4 kv = ((const float4*)g_k)[i];
        ((__half2*)g_kh)[2*i]   = __halves2half2(__float2half_rn(kv.x), __float2half_rn(kv.y));
        ((__half2*)g_kh)[2*i+1] = __halves2half2(__float2half_rn(kv.z), __float2half_rn(kv.w));
    }
}

// ---------------- split o (hi/lo) ------------------------------------------------
__global__ void split_o() {
    long i  = (long)blockIdx.x * blockDim.x + threadIdx.x;
    long st = (long)gridDim.x * blockDim.x;
    long n4 = (long)N_ * H_ / 4;
    for (; i < n4; i += st) {
        float4 v = ((const float4*)g_o)[i];
        half h0, l0, h1, l1, h2, l2, h3, l3;
        split_f32(v.x, h0, l0); split_f32(v.y, h1, l1);
        split_f32(v.z, h2, l2); split_f32(v.w, h3, l3);
        ((__half2*)g_oh)[2*i]   = __halves2half2(h0, h1);
        ((__half2*)g_oh)[2*i+1] = __halves2half2(h2, h3);
        ((__half2*)g_ol)[2*i]   = __halves2half2(l0, l1);
        ((__half2*)g_ol)[2*i+1] = __halves2half2(l2, l3);
    }
}

// ---------------- transpose v -> vT (fp16 hi only), per batch --------------------
__global__ void tsplit_h() {
    __shared__ float tsm[32][33];
    size_t zo = (size_t)blockIdx.z * T_ * H_;
    const float* in = g_v + zo;
    half* oh = g_vTh + zo;
    int c0 = blockIdx.x * 32, r0 = blockIdx.y * 32;
    int tx = threadIdx.x, ty = threadIdx.y;
    #pragma unroll
    for (int i = ty; i < 32; i += 8) tsm[i][tx] = in[(size_t)(r0 + i) * H_ + c0 + tx];
    __syncthreads();
    #pragma unroll
    for (int i = ty; i < 32; i += 8)
        oh[(size_t)(c0 + i) * T_ + r0 + tx] = __float2half_rn(tsm[tx][i]);
}

// ---------------- softmax over S rows, writing fp16 (single) ---------------------
__global__ void softmax_split() {
    __shared__ float buf[T_];
    __shared__ float red[8];
    const float4* S4 = (const float4*)(g_S + (size_t)blockIdx.x * T_);
    __half2* sh = (__half2*)(g_Sh + (size_t)blockIdx.x * T_);
    int tid = threadIdx.x, lane = tid & 31, wrp = tid >> 5;

    float mx = -3.4e38f;
    #pragma unroll
    for (int it = 0; it < 2; it++) {
        int j = tid + it * 256;
        float4 v = S4[j];
        ((float4*)buf)[j] = v;
        mx = fmaxf(mx, fmaxf(fmaxf(v.x, v.y), fmaxf(v.z, v.w)));
    }
    #pragma unroll
    for (int o = 16; o > 0; o >>= 1) mx = fmaxf(mx, __shfl_xor_sync(0xffffffffu, mx, o));
    if (lane == 0) red[wrp] = mx;
    __syncthreads();
    mx = red[lane & 7];
    #pragma unroll
    for (int o = 4; o > 0; o >>= 1) mx = fmaxf(mx, __shfl_xor_sync(0xffffffffu, mx, o));

    float sum = 0.f;
    #pragma unroll
    for (int it = 0; it < 2; it++) {
        int j = tid + it * 256;
        float4 v = ((float4*)buf)[j];
        v.x = __expf(v.x - mx); v.y = __expf(v.y - mx);
        v.z = __expf(v.z - mx); v.w = __expf(v.w - mx);
        ((float4*)buf)[j] = v;
        sum += v.x + v.y + v.z + v.w;
    }
    #pragma unroll
    for (int o = 16; o > 0; o >>= 1) sum += __shfl_xor_sync(0xffffffffu, sum, o);
    __syncthreads();
    if (lane == 0) red[wrp] = sum;
    __syncthreads();
    sum = red[lane & 7];
    #pragma unroll
    for (int o = 4; o > 0; o >>= 1) sum += __shfl_xor_sync(0xffffffffu, sum, o);
    float inv = 1.0f / sum;

    #pragma unroll
    for (int it = 0; it < 2; it++) {
        int j = tid + it * 256;
        float4 v = ((float4*)buf)[j];
        sh[2*j]   = __halves2half2(__float2half_rn(v.x * inv), __float2half_rn(v.y * inv));
        sh[2*j+1] = __halves2half2(__float2half_rn(v.z * inv), __float2half_rn(v.w * inv));
    }
}

// ---------------- launch ---------------------------------------------------------
extern "C" void kernel_launch(void* const* d_in, const int* in_sizes, int n_in,
                              void* d_out, int out_size)
{
    const float* x     = (const float*)d_in[0];
    const float* sim   = (const float*)d_in[1];
    const float* gates = (const float*)d_in[2];
    const float* qp    = (const float*)d_in[3];
    const float* kp    = (const float*)d_in[4];
    const float* vp    = (const float*)d_in[5];
    const float* op    = (const float*)d_in[6];
    float* outp = (float*)d_out;

    float *q, *k, *v, *o, *S, *wt;
    int *cnt, *idx;
    half *xh, *xl, *qh, *ql, *kh, *vTh, *oh, *ol, *Sh;
    half *wqh, *wkh, *wvh, *woh;
    cudaGetSymbolAddress((void**)&q, g_q);     cudaGetSymbolAddress((void**)&k, g_k);
    cudaGetSymbolAddress((void**)&v, g_v);     cudaGetSymbolAddress((void**)&o, g_o);
    cudaGetSymbolAddress((void**)&S, g_S);
    cudaGetSymbolAddress((void**)&cnt, g_cnt); cudaGetSymbolAddress((void**)&idx, g_idx);
    cudaGetSymbolAddress((void**)&wt, g_wt);
    cudaGetSymbolAddress((void**)&xh, g_xh);   cudaGetSymbolAddress((void**)&xl, g_xl);
    cudaGetSymbolAddress((void**)&qh, g_qh);   cudaGetSymbolAddress((void**)&ql, g_ql);
    cudaGetSymbolAddress((void**)&kh, g_kh);
    cudaGetSymbolAddress((void**)&vTh, g_vTh);
    cudaGetSymbolAddress((void**)&oh, g_oh);   cudaGetSymbolAddress((void**)&ol, g_ol);
    cudaGetSymbolAddress((void**)&Sh, g_Sh);
    cudaGetSymbolAddress((void**)&wqh, g_wqh); cudaGetSymbolAddress((void**)&wkh, g_wkh);
    cudaGetSymbolAddress((void**)&wvh, g_wvh); cudaGetSymbolAddress((void**)&woh, g_woh);

    cudaFuncSetAttribute(hm_gemm<true,  true,  true >, cudaFuncAttributeMaxDynamicSharedMemorySize, DSM_BYTES);
    cudaFuncSetAttribute(hm_gemm<false, false, true >, cudaFuncAttributeMaxDynamicSharedMemorySize, DSM_BYTES);
    cudaFuncSetAttribute(hm_gemm<false, true,  false>, cudaFuncAttributeMaxDynamicSharedMemorySize, DSM_BYTES);

    prep_kernel<<<1, 512>>>(sim, gates);                               // 1
    gating_kernel<<<N_/8, 256>>>(x, sim);                              // 2
    prep_operands<<<dim3(4, 32, 96), 256>>>(qp, kp, vp, op, x, outp);  // 3

    // 4: QKV MoE dispatch (gathered, weighted atomic accumulate, split-K x2)
    {
        TCArgs a{};
        a.Ah = xh; a.Al = xl;
        a.Bh0 = wqh; a.Bh1 = wkh; a.Bh2 = wvh;
        a.C0 = q; a.C1 = k; a.C2 = v;
        a.sAz = 0; a.sBz = (long)H_*C_; a.sCz = 0;
        a.lda = C_; a.ldb = C_; a.ldc = H_;
        a.M = N_; a.K = C_; a.nxb = 1; a.nsplit = 2; a.ksplit = 512;
        a.alpha = 1.f; a.cnt = cnt; a.idxB = idx; a.wtB = wt;
        hm_gemm<true, true, true><<<dim3(3, 64, 32), 256, DSM_BYTES>>>(a);
    }

    split_qk<<<512, 256>>>();                                          // 5
    tsplit_h<<<dim3(H_/32, T_/32, B_), dim3(32,8)>>>();                // 6

    // 7: S = Q K^T / sqrt(H)
    {
        TCArgs a{};
        a.Ah = qh; a.Al = ql;
        a.Bh0 = kh; a.Bh1 = kh; a.Bh2 = kh;
        a.C0 = S; a.C1 = S; a.C2 = S;
        a.sAz = (long)T_*H_; a.sBz = (long)T_*H_; a.sCz = (long)T_*T_;
        a.lda = H_; a.ldb = H_; a.ldc = T_;
        a.M = T_; a.K = H_; a.nxb = 16; a.nsplit = 1; a.ksplit = H_;
        a.alpha = 0.08838834764831845f;
        hm_gemm<false, false, true><<<dim3(16, 16, 4), 256, DSM_BYTES>>>(a);
    }

    softmax_split<<<B_*T_, 256>>>();                                   // 8

    // 9: O = P V   (single-term fp16 P, split-K x8, atomic accumulate into o f32)
    {
        TCArgs a{};
        a.Ah = Sh; a.Al = Sh;
        a.Bh0 = vTh; a.Bh1 = vTh; a.Bh2 = vTh;
        a.C0 = o; a.C1 = o; a.C2 = o;
        a.sAz = (long)T_*T_; a.sBz = (long)H_*T_; a.sCz = (long)T_*H_;
        a.lda = T_; a.ldb = T_; a.ldc = H_;
        a.M = T_; a.K = T_; a.nxb = 1; a.nsplit = 8; a.ksplit = 256;
        a.alpha = 1.f;
        hm_gemm<false, true, false><<<dim3(1, 16, 32), 256, DSM_BYTES>>>(a);
    }

    split_o<<<512, 256>>>();                                           // 10

    // 11: output MoE combine (gathered, weighted atomic accumulate into out)
    {
        TCArgs a{};
        a.Ah = oh; a.Al = ol;
        a.Bh0 = woh; a.Bh1 = woh; a.Bh2 = woh;
        a.C0 = outp; a.C1 = outp; a.C2 = outp;
        a.sAz = 0; a.sBz = (long)C_*H_; a.sCz = 0;
        a.lda = H_; a.ldb = H_; a.ldc = C_;
        a.M = N_; a.K = H_; a.nxb = 8; a.nsplit = 1; a.ksplit = H_;
        a.alpha = 1.f; a.cnt = cnt; a.idxB = idx; a.wtB = wt;
        hm_gemm<true, true, true><<<dim3(8, 64, 16), 256, DSM_BYTES>>>(a);
    }
}

// round 16
// speedup vs baseline: 1.2049x; 1.0542x over previous
#include <cuda_runtime.h>
#include <cuda_fp16.h>
#include <math.h>
#include <stdint.h>

#define B_ 4
#define T_ 2048
#define C_ 1024
#define H_ 128
#define E_ 16
#define N_ (B_*T_)   /* 8192 tokens */

// ---------------- scratch (allocation-free: __device__ globals) ----------------
__device__ float g_q[(size_t)N_*H_];
__device__ float g_k[(size_t)N_*H_];
__device__ float g_v[(size_t)N_*H_];
__device__ float g_o[(size_t)N_*H_];
__device__ float g_rsum[N_];                      // attention row sums (exp)

__device__ half g_xh[(size_t)N_*C_],  g_xl[(size_t)N_*C_];
__device__ half g_qh[(size_t)N_*H_],  g_ql[(size_t)N_*H_];
__device__ half g_kh[(size_t)N_*H_];
__device__ half g_vTh[(size_t)N_*H_];                         // [B][H][T]
__device__ half g_oh[(size_t)N_*H_],  g_ol[(size_t)N_*H_];
__device__ half g_Sh[(size_t)B_*T_*T_];                       // unnormalized exp(s-8)
__device__ half g_wqh[(size_t)E_*H_*C_];                      // [E][H][C]
__device__ half g_wkh[(size_t)E_*H_*C_];
__device__ half g_wvh[(size_t)E_*H_*C_];
__device__ half g_woh[(size_t)E_*C_*H_];                      // [E][C][H]

__device__ int   g_cnt[E_];
__device__ int   g_idx[(size_t)E_*N_];
__device__ float g_wt[(size_t)E_*N_];
__device__ float g_invsn[E_];
__device__ float g_sig[E_];

// ---------------- mma.sync / ldmatrix / cp.async helpers (baseline PTX) ---------
#define MMA16816(d, A0, A1, A2, A3, Bv0, Bv1) \
    asm volatile("mma.sync.aligned.m16n8k16.row.col.f32.f16.f16.f32 " \
        "{%0,%1,%2,%3},{%4,%5,%6,%7},{%8,%9},{%0,%1,%2,%3};" \
        : "+f"((d)[0]), "+f"((d)[1]), "+f"((d)[2]), "+f"((d)[3]) \
        : "r"(A0), "r"(A1), "r"(A2), "r"(A3), "r"(Bv0), "r"(Bv1))

#define LDSM4(r0, r1, r2, r3, addr) \
    asm volatile("ldmatrix.sync.aligned.m8n8.x4.shared.b16 {%0,%1,%2,%3}, [%4];" \
        : "=r"(r0), "=r"(r1), "=r"(r2), "=r"(r3) : "r"(addr))

#define CPA16(dst, src) \
    asm volatile("cp.async.cg.shared.global [%0], [%1], 16;" :: "r"(dst), "l"(src))

__device__ __forceinline__ uint32_t smem_u32(const void* p) {
    uint32_t a;
    asm("{ .reg .u64 t; cvta.to.shared.u64 t, %1; cvt.u32.u64 %0, t; }" : "=r"(a) : "l"(p));
    return a;
}

__device__ __forceinline__ void split_f32(float v, half& h, half& l) {
    h = __float2half_rn(v);
    l = __float2half_rn(v - __half2float(h));
}

// ---------------- HMMA GEMM -------------------------------------------------------
// TWOTERM: D = (Ah+Al) * Bh ; else D = Ah * Bh
// EXPEPI : epilogue stores exp(alpha*acc - 8) to fp16 D and row-sums to rsum
struct TCArgs {
    const half *Ah, *Al;
    const half *Bh0, *Bh1, *Bh2;
    float *C0, *C1, *C2;
    half  *D;
    float *rsum;
    long sAz, sBz, sCz;
    int  lda, ldb, ldc;
    int  M, K, nxb, nsplit, ksplit;
    float alpha;
    const int* cnt; const int* idxB; const float* wtB;
};

#define PITCH 20   /* row pitch in b32 units: 16 b32 (32 fp16) + 4 pad */
#define TILE_U32 (128*PITCH)
#define DSM_BYTES (3*3*TILE_U32*4)   /* 3 stages x 3 tiles = 92160 B */

template<bool GATHER, bool ATOMIC, bool TWOTERM, bool EXPEPI>
__global__ void __launch_bounds__(256, 2) hm_gemm(TCArgs a)
{
    int zb  = blockIdx.z / a.nsplit;
    int sp  = blockIdx.z % a.nsplit;
    int mat = blockIdx.x / a.nxb;
    int n0  = (blockIdx.x % a.nxb) * 128;

    int Mz = a.M;
    const int*   gidx = nullptr;
    const float* gwt  = nullptr;
    if (GATHER) {
        Mz   = a.cnt[zb];
        gidx = a.idxB + (size_t)zb * N_;
        gwt  = a.wtB  + (size_t)zb * N_;
    }
    int m0 = blockIdx.y * 128;
    if (m0 >= Mz) return;

    const half* Ah = a.Ah + (size_t)zb * a.sAz;
    const half* Al = a.Al + (size_t)zb * a.sAz;
    const half* Bh = (mat == 0 ? a.Bh0 : mat == 1 ? a.Bh1 : a.Bh2) + (size_t)zb * a.sBz;
    float*      C  = (mat == 0 ? a.C0  : mat == 1 ? a.C1  : a.C2)  + (size_t)zb * a.sCz;

    extern __shared__ uint32_t dsm[];
    uint32_t smbase = smem_u32(dsm);

    __shared__ int   s_idx[128];
    __shared__ float s_wt[128];

    int tid  = threadIdx.x;
    int lane = tid & 31, wid = tid >> 5;
    int g = lane >> 2, t = lane & 3;
    int wm = wid & 1, wn = wid >> 1;          // warp grid 2 (m) x 4 (n)
    int mbw = wm * 64, nbw = wn * 32;

    if (GATHER) {
        for (int i = tid; i < 128; i += 256) {
            int r = m0 + i;
            bool v = r < Mz;
            s_idx[i] = v ? gidx[r] : 0;
            s_wt[i]  = v ? gwt[r] : 0.f;
        }
    }
    __syncthreads();

    float acc[4][4][4];
    #pragma unroll
    for (int i = 0; i < 4; i++)
        #pragma unroll
        for (int j = 0; j < 4; j++)
            #pragma unroll
            for (int c = 0; c < 4; c++) acc[i][j][c] = 0.f;

    int kb = sp * a.ksplit;
    int ke = kb + a.ksplit; if (ke > a.K) ke = a.K;
    int nch = (ke - kb) >> 5;

    // per-thread global load coordinates (fixed across k-chunks)
    int f0row = tid >> 2,          f0kq = tid & 3;
    int f1row = (tid + 256) >> 2,  f1kq = (tid + 256) & 3;
    long ar0 = GATHER ? (long)s_idx[f0row] : (long)(m0 + f0row);
    long ar1 = GATHER ? (long)s_idx[f1row] : (long)(m0 + f1row);
    long br0 = (long)(n0 + f0row), br1 = (long)(n0 + f1row);
    uint32_t so0 = (uint32_t)(f0row * PITCH + f0kq * 4) * 4u;
    uint32_t so1 = (uint32_t)(f1row * PITCH + f1kq * 4) * 4u;

    // ldmatrix lane-address offsets (bytes)
    int jj = lane >> 3, rr = lane & 7;
    uint32_t aoff = (uint32_t)(((jj & 1) * 8 + rr) * PITCH + (jj >> 1) * 4) * 4u;
    uint32_t boff = (uint32_t)(((jj >> 1) * 8 + rr) * PITCH + (jj & 1) * 4) * 4u;
    uint32_t baseA = smbase + (uint32_t)(mbw * PITCH) * 4u + aoff;
    uint32_t baseB = smbase + (uint32_t)(nbw * PITCH) * 4u + boff;
    const uint32_t TB = (uint32_t)TILE_U32 * 4u;   // tile stride in bytes

    // chunk loader into stage s (tiles: Ah, [Al], Bh)
    auto load_chunk = [&](int k0, int s) {
        uint32_t bb = (uint32_t)(s * 3) * TB;
        CPA16(smbase + bb + 0*TB + so0, Ah + ar0 * (long)a.lda + k0 + f0kq * 8);
        CPA16(smbase + bb + 0*TB + so1, Ah + ar1 * (long)a.lda + k0 + f1kq * 8);
        if (TWOTERM) {
            CPA16(smbase + bb + 1*TB + so0, Al + ar0 * (long)a.lda + k0 + f0kq * 8);
            CPA16(smbase + bb + 1*TB + so1, Al + ar1 * (long)a.lda + k0 + f1kq * 8);
        }
        CPA16(smbase + bb + 2*TB + so0, Bh + br0 * (long)a.ldb + k0 + f0kq * 8);
        CPA16(smbase + bb + 2*TB + so1, Bh + br1 * (long)a.ldb + k0 + f1kq * 8);
    };

    // 3-stage pipeline prologue
    load_chunk(kb, 0);
    asm volatile("cp.async.commit_group;" ::: "memory");
    if (nch > 1) {
        load_chunk(kb + 32, 1);
        asm volatile("cp.async.commit_group;" ::: "memory");
    }

    int stage = 0;
    for (int i = 0; i < nch; i++) {
        if (i < nch - 1) asm volatile("cp.async.wait_group 1;" ::: "memory");
        else             asm volatile("cp.async.wait_group 0;" ::: "memory");
        __syncthreads();

        if (i + 2 < nch) {
            int s2 = stage + 2; if (s2 >= 3) s2 -= 3;
            load_chunk(kb + (i + 2) * 32, s2);
            asm volatile("cp.async.commit_group;" ::: "memory");
        }

        uint32_t bb = (uint32_t)(stage * 3) * TB;
        uint32_t bAh = baseA + bb + 0*TB, bAl = baseA + bb + 1*TB;
        uint32_t bBh = baseB + bb + 2*TB;

        #pragma unroll
        for (int kk = 0; kk < 2; kk++) {
            uint32_t kadd = (uint32_t)(kk * 8) * 4u;
            uint32_t bh[4][2];
            #pragma unroll
            for (int np = 0; np < 2; np++) {
                uint32_t ba = (uint32_t)(np * 16 * PITCH) * 4u + kadd;
                LDSM4(bh[2*np][0], bh[2*np][1], bh[2*np+1][0], bh[2*np+1][1], bBh + ba);
            }
            #pragma unroll
            for (int mt = 0; mt < 4; mt++) {
                uint32_t ma = (uint32_t)(mt * 16 * PITCH) * 4u + kadd;
                uint32_t ah0, ah1, ah2, ah3;
                LDSM4(ah0, ah1, ah2, ah3, bAh + ma);
                if (TWOTERM) {
                    uint32_t al0, al1, al2, al3;
                    LDSM4(al0, al1, al2, al3, bAl + ma);
                    #pragma unroll
                    for (int nt = 0; nt < 4; nt++) {
                        MMA16816(acc[mt][nt], ah0, ah1, ah2, ah3, bh[nt][0], bh[nt][1]);
                        MMA16816(acc[mt][nt], al0, al1, al2, al3, bh[nt][0], bh[nt][1]);
                    }
                } else {
                    #pragma unroll
                    for (int nt = 0; nt < 4; nt++)
                        MMA16816(acc[mt][nt], ah0, ah1, ah2, ah3, bh[nt][0], bh[nt][1]);
                }
            }
        }
        stage = stage + 1; if (stage >= 3) stage -= 3;
    }

    // ---------------- epilogue ----------------
    if (EXPEPI) {
        // p = exp(alpha*s - 8) -> fp16 D ; row sums -> rsum (f32 atomics)
        half*  Dp = a.D    + (size_t)zb * (size_t)T_ * T_;
        float* rs = a.rsum + (size_t)zb * T_;
        #pragma unroll
        for (int mt = 0; mt < 4; mt++) {
            #pragma unroll
            for (int half_ = 0; half_ < 2; half_++) {
                int lr = mbw + mt * 16 + g + half_ * 8;
                long orow = m0 + lr;
                half* dp = Dp + orow * (long)T_ + n0 + nbw;
                float rsl = 0.f;
                #pragma unroll
                for (int nt = 0; nt < 4; nt++) {
                    int col = nt * 8 + 2 * t;
                    float p0 = __expf(acc[mt][nt][half_ * 2 + 0] * a.alpha - 8.f);
                    float p1 = __expf(acc[mt][nt][half_ * 2 + 1] * a.alpha - 8.f);
                    *(__half2*)(dp + col) = __halves2half2(__float2half_rn(p0), __float2half_rn(p1));
                    rsl += p0 + p1;
                }
                rsl += __shfl_xor_sync(0xffffffffu, rsl, 1);
                rsl += __shfl_xor_sync(0xffffffffu, rsl, 2);
                if (t == 0) atomicAdd(rs + orow, rsl);
            }
        }
    } else {
        #pragma unroll
        for (int mt = 0; mt < 4; mt++) {
            #pragma unroll
            for (int half_ = 0; half_ < 2; half_++) {
                int lr = mbw + mt * 16 + g + half_ * 8;
                bool rv; long orow; float sc;
                if (GATHER) { rv = (m0 + lr) < Mz; orow = s_idx[lr]; sc = a.alpha * s_wt[lr]; }
                else        { rv = true;           orow = m0 + lr;   sc = a.alpha; }
                if (rv) {
                    float* cp = C + orow * (long)a.ldc + n0 + nbw;
                    #pragma unroll
                    for (int nt = 0; nt < 4; nt++) {
                        int col = nt * 8 + 2 * t;
                        float v0 = acc[mt][nt][half_ * 2 + 0] * sc;
                        float v1 = acc[mt][nt][half_ * 2 + 1] * sc;
                        if (ATOMIC) { atomicAdd(cp + col, v0); atomicAdd(cp + col + 1, v1); }
                        else        { float2 vv; vv.x = v0; vv.y = v1; *(float2*)(cp + col) = vv; }
                    }
                }
            }
        }
    }
}

// ---------------- sim-matrix column norms + sigmoid(gates) + counter reset -------
__global__ void prep_kernel(const float* __restrict__ sim, const float* __restrict__ gates) {
    int e = threadIdx.x >> 5, lane = threadIdx.x & 31;
    if (threadIdx.x < E_) g_cnt[threadIdx.x] = 0;
    float s = 0.f;
    for (int c = lane; c < C_; c += 32) { float v = sim[(size_t)c*E_ + e]; s += v*v; }
    #pragma unroll
    for (int o = 16; o > 0; o >>= 1) s += __shfl_xor_sync(0xffffffffu, s, o);
    if (lane == 0) {
        g_invsn[e] = 1.0f / fmaxf(sqrtf(s), 1e-12f);
        g_sig[e]   = 1.0f / (1.0f + expf(-gates[e]));
    }
}

// ---------------- gating (one warp per token) ------------------------------------
__global__ void gating_kernel(const float* __restrict__ x, const float* __restrict__ sim) {
    int tok  = blockIdx.x * (blockDim.x >> 5) + (threadIdx.x >> 5);
    int lane = threadIdx.x & 31;
    if (tok >= N_) return;
    const float* xr = x + (size_t)tok * C_;

    float dot[E_];
    #pragma unroll
    for (int e = 0; e < E_; e++) dot[e] = 0.f;
    float nrm = 0.f;
    for (int c = lane; c < C_; c += 32) {
        float xv = xr[c];
        nrm += xv * xv;
        const float4* s4 = (const float4*)(sim + (size_t)c * E_);
        float4 r0 = s4[0], r1 = s4[1], r2 = s4[2], r3 = s4[3];
        dot[0]+=xv*r0.x; dot[1]+=xv*r0.y; dot[2]+=xv*r0.z; dot[3]+=xv*r0.w;
        dot[4]+=xv*r1.x; dot[5]+=xv*r1.y; dot[6]+=xv*r1.z; dot[7]+=xv*r1.w;
        dot[8]+=xv*r2.x; dot[9]+=xv*r2.y; dot[10]+=xv*r2.z; dot[11]+=xv*r2.w;
        dot[12]+=xv*r3.x; dot[13]+=xv*r3.y; dot[14]+=xv*r3.z; dot[15]+=xv*r3.w;
    }
    #pragma unroll
    for (int o = 16; o > 0; o >>= 1) {
        nrm += __shfl_xor_sync(0xffffffffu, nrm, o);
        #pragma unroll
        for (int e = 0; e < E_; e++) dot[e] += __shfl_xor_sync(0xffffffffu, dot[e], o);
    }
    float invx = 1.0f / fmaxf(sqrtf(nrm), 1e-12f);

    float logit[E_], gated[E_];
    unsigned msk = 0u;
    #pragma unroll
    for (int e = 0; e < E_; e++) {
        logit[e] = dot[e] * invx * g_invsn[e] - g_sig[e];
        gated[e] = fmaxf(logit[e], 0.f);
        if (logit[e] > 0.f) msk |= (1u << e);
    }
    if (msk == 0u) {
        float m1 = -3.4e38f; int i1 = 0;
        #pragma unroll
        for (int e = 0; e < E_; e++) if (logit[e] > m1) { m1 = logit[e]; i1 = e; }
        float m2 = -3.4e38f; int i2 = 0;
        #pragma unroll
        for (int e = 0; e < E_; e++) if (e != i1 && logit[e] > m2) { m2 = logit[e]; i2 = e; }
        msk = (1u << i1) | (1u << i2);
    }
    float mx = -3.4e38f;
    #pragma unroll
    for (int e = 0; e < E_; e++) if ((msk >> e) & 1u) mx = fmaxf(mx, gated[e]);
    float wv[E_]; float sum = 0.f;
    #pragma unroll
    for (int e = 0; e < E_; e++) {
        wv[e] = ((msk >> e) & 1u) ? expf(gated[e] - mx) : 0.f;
        sum += wv[e];
    }
    float inv = 1.0f / sum;
    #pragma unroll
    for (int e = 0; e < E_; e++) {
        if (lane == e && ((msk >> e) & 1u)) {
            int pos = atomicAdd(&g_cnt[e], 1);
            g_idx[(size_t)e * N_ + pos] = tok;
            g_wt [(size_t)e * N_ + pos] = wv[e] * inv;
        }
    }
}

// ---------------- fused operand prep ---------------------------------------------
__global__ void prep_operands(const float* __restrict__ qp, const float* __restrict__ kp,
                              const float* __restrict__ vp, const float* __restrict__ op,
                              const float* __restrict__ x,  float* __restrict__ out)
{
    int z = blockIdx.z;
    int tid = threadIdx.x;
    if (z < 64) {
        __shared__ float tsm[32][33];
        int e = z >> 2, mat = z & 3;
        const float* in;
        half* oh;
        int R, Cc, c0, r0;
        if (mat == 0)      { in = qp; oh = g_wqh; }
        else if (mat == 1) { in = kp; oh = g_wkh; }
        else if (mat == 2) { in = vp; oh = g_wvh; }
        else               { in = op; oh = g_woh; }
        if (mat < 3) { R = C_; Cc = H_; c0 = blockIdx.x * 32; r0 = blockIdx.y * 32; }
        else         { R = H_; Cc = C_; c0 = blockIdx.y * 32; r0 = blockIdx.x * 32; }
        size_t zo = (size_t)e * R * Cc;
        in += zo; oh += zo;
        int tx = tid & 31, ty = tid >> 5;
        #pragma unroll
        for (int i = ty; i < 32; i += 8) tsm[i][tx] = in[(size_t)(r0 + i) * Cc + c0 + tx];
        __syncthreads();
        #pragma unroll
        for (int i = ty; i < 32; i += 8)
            oh[(size_t)(c0 + i) * R + r0 + tx] = __float2half_rn(tsm[tx][i]);
    } else {
        long flat = (long)(z - 64) * 128 + blockIdx.y * 4 + blockIdx.x;  // 0..4095
        const long STRIDE = 2048L * 256;
        if (flat < 2048) {
            long i = flat * 256 + tid;
            long n4 = (long)N_ * C_ / 4;
            for (; i < n4; i += STRIDE) {
                float4 v = ((const float4*)x)[i];
                half h0, l0, h1, l1, h2, l2, h3, l3;
                split_f32(v.x, h0, l0); split_f32(v.y, h1, l1);
                split_f32(v.z, h2, l2); split_f32(v.w, h3, l3);
                ((__half2*)g_xh)[2*i]   = __halves2half2(h0, h1);
                ((__half2*)g_xh)[2*i+1] = __halves2half2(h2, h3);
                ((__half2*)g_xl)[2*i]   = __halves2half2(l0, l1);
                ((__half2*)g_xl)[2*i+1] = __halves2half2(l2, l3);
            }
        } else {
            long i = (flat - 2048) * 256 + tid;
            float4 zf = make_float4(0.f, 0.f, 0.f, 0.f);
            long nqkv = (long)N_ * H_ / 4;
            for (long j = i; j < nqkv; j += STRIDE) {
                ((float4*)g_q)[j] = zf; ((float4*)g_k)[j] = zf;
                ((float4*)g_v)[j] = zf; ((float4*)g_o)[j] = zf;
            }
            long nout = (long)N_ * C_ / 4;
            for (long j = i; j < nout; j += STRIDE) ((float4*)out)[j] = zf;
            for (long j = i; j < N_; j += STRIDE) g_rsum[j] = 0.f;
        }
    }
}

// ---------------- split q (hi/lo) + convert k (hi) -------------------------------
__global__ void split_qk() {
    long i  = (long)blockIdx.x * blockDim.x + threadIdx.x;
    long st = (long)gridDim.x * blockDim.x;
    long n4 = (long)N_ * H_ / 4;
    for (; i < n4; i += st) {
        float4 qv = ((const float4*)g_q)[i];
        half h0, l0, h1, l1, h2, l2, h3, l3;
        split_f32(qv.x, h0, l0); split_f32(qv.y, h1, l1);
        split_f32(qv.z, h2, l2); split_f32(qv.w, h3, l3);
        ((__half2*)g_qh)[2*i]   = __halves2half2(h0, h1);
        ((__half2*)g_qh)[2*i+1] = __halves2half2(h2, h3);
        ((__half2*)g_ql)[2*i]   = __halves2half2(l0, l1);
        ((__half2*)g_ql)[2*i+1] = __halves2half2(l2, l3);
        float4 kv = ((const float4*)g_k)[i];
        ((__half2*)g_kh)[2*i]   = __halves2half2(__float2half_rn(kv.x), __float2half_rn(kv.y));
        ((__half2*)g_kh)[2*i+1] = __halves2half2(__float2half_rn(kv.z), __float2half_rn(kv.w));
    }
}

// ---------------- normalize o by rsum + split hi/lo ------------------------------
__global__ void split_o() {
    long i  = (long)blockIdx.x * blockDim.x + threadIdx.x;
    long st = (long)gridDim.x * blockDim.x;
    long n4 = (long)N_ * H_ / 4;
    for (; i < n4; i += st) {
        long row = i >> 5;                      // 32 float4 per 128-elem row
        float inv = 1.0f / g_rsum[row];
        float4 v = ((const float4*)g_o)[i];
        v.x *= inv; v.y *= inv; v.z *= inv; v.w *= inv;
        half h0, l0, h1, l1, h2, l2, h3, l3;
        split_f32(v.x, h0, l0); split_f32(v.y, h1, l1);
        split_f32(v.z, h2, l2); split_f32(v.w, h3, l3);
        ((__half2*)g_oh)[2*i]   = __halves2half2(h0, h1);
        ((__half2*)g_oh)[2*i+1] = __halves2half2(h2, h3);
        ((__half2*)g_ol)[2*i]   = __halves2half2(l0, l1);
        ((__half2*)g_ol)[2*i+1] = __halves2half2(l2, l3);
    }
}

// ---------------- transpose v -> vT (fp16 hi only), per batch --------------------
__global__ void tsplit_h() {
    __shared__ float tsm[32][33];
    size_t zo = (size_t)blockIdx.z * T_ * H_;
    const float* in = g_v + zo;
    half* oh = g_vTh + zo;
    int c0 = blockIdx.x * 32, r0 = blockIdx.y * 32;
    int tx = threadIdx.x, ty = threadIdx.y;
    #pragma unroll
    for (int i = ty; i < 32; i += 8) tsm[i][tx] = in[(size_t)(r0 + i) * H_ + c0 + tx];
    __syncthreads();
    #pragma unroll
    for (int i = ty; i < 32; i += 8)
        oh[(size_t)(c0 + i) * T_ + r0 + tx] = __float2half_rn(tsm[tx][i]);
}

// ---------------- launch ---------------------------------------------------------
extern "C" void kernel_launch(void* const* d_in, const int* in_sizes, int n_in,
                              void* d_out, int out_size)
{
    const float* x     = (const float*)d_in[0];
    const float* sim   = (const float*)d_in[1];
    const float* gates = (const float*)d_in[2];
    const float* qp    = (const float*)d_in[3];
    const float* kp    = (const float*)d_in[4];
    const float* vp    = (const float*)d_in[5];
    const float* op    = (const float*)d_in[6];
    float* outp = (float*)d_out;

    float *q, *k, *v, *o, *rsum, *wt;
    int *cnt, *idx;
    half *xh, *xl, *qh, *ql, *kh, *vTh, *oh, *ol, *Sh;
    half *wqh, *wkh, *wvh, *woh;
    cudaGetSymbolAddress((void**)&q, g_q);     cudaGetSymbolAddress((void**)&k, g_k);
    cudaGetSymbolAddress((void**)&v, g_v);     cudaGetSymbolAddress((void**)&o, g_o);
    cudaGetSymbolAddress((void**)&rsum, g_rsum);
    cudaGetSymbolAddress((void**)&cnt, g_cnt); cudaGetSymbolAddress((void**)&idx, g_idx);
    cudaGetSymbolAddress((void**)&wt, g_wt);
    cudaGetSymbolAddress((void**)&xh, g_xh);   cudaGetSymbolAddress((void**)&xl, g_xl);
    cudaGetSymbolAddress((void**)&qh, g_qh);   cudaGetSymbolAddress((void**)&ql, g_ql);
    cudaGetSymbolAddress((void**)&kh, g_kh);
    cudaGetSymbolAddress((void**)&vTh, g_vTh);
    cudaGetSymbolAddress((void**)&oh, g_oh);   cudaGetSymbolAddress((void**)&ol, g_ol);
    cudaGetSymbolAddress((void**)&Sh, g_Sh);
    cudaGetSymbolAddress((void**)&wqh, g_wqh); cudaGetSymbolAddress((void**)&wkh, g_wkh);
    cudaGetSymbolAddress((void**)&wvh, g_wvh); cudaGetSymbolAddress((void**)&woh, g_woh);

    cudaFuncSetAttribute(hm_gemm<true,  true,  true,  false>, cudaFuncAttributeMaxDynamicSharedMemorySize, DSM_BYTES);
    cudaFuncSetAttribute(hm_gemm<false, false, true,  true >, cudaFuncAttributeMaxDynamicSharedMemorySize, DSM_BYTES);
    cudaFuncSetAttribute(hm_gemm<false, true,  false, false>, cudaFuncAttributeMaxDynamicSharedMemorySize, DSM_BYTES);

    prep_kernel<<<1, 512>>>(sim, gates);                               // 1
    gating_kernel<<<N_/8, 256>>>(x, sim);                              // 2
    prep_operands<<<dim3(4, 32, 96), 256>>>(qp, kp, vp, op, x, outp);  // 3

    // 4: QKV MoE dispatch (gathered, weighted atomic accumulate, split-K x2)
    {
        TCArgs a{};
        a.Ah = xh; a.Al = xl;
        a.Bh0 = wqh; a.Bh1 = wkh; a.Bh2 = wvh;
        a.C0 = q; a.C1 = k; a.C2 = v;
        a.sAz = 0; a.sBz = (long)H_*C_; a.sCz = 0;
        a.lda = C_; a.ldb = C_; a.ldc = H_;
        a.M = N_; a.K = C_; a.nxb = 1; a.nsplit = 2; a.ksplit = 512;
        a.alpha = 1.f; a.cnt = cnt; a.idxB = idx; a.wtB = wt;
        hm_gemm<true, true, true, false><<<dim3(3, 64, 32), 256, DSM_BYTES>>>(a);
    }

    split_qk<<<512, 256>>>();                                          // 5
    tsplit_h<<<dim3(H_/32, T_/32, B_), dim3(32,8)>>>();                // 6

    // 7: P = exp(Q K^T / sqrt(H) - 8)  (fused softmax epilogue; rowsums to rsum)
    {
        TCArgs a{};
        a.Ah = qh; a.Al = ql;
        a.Bh0 = kh; a.Bh1 = kh; a.Bh2 = kh;
        a.C0 = outp; a.C1 = outp; a.C2 = outp;   // unused in EXPEPI
        a.D = Sh; a.rsum = rsum;
        a.sAz = (long)T_*H_; a.sBz = (long)T_*H_; a.sCz = 0;
        a.lda = H_; a.ldb = H_; a.ldc = T_;
        a.M = T_; a.K = H_; a.nxb = 16; a.nsplit = 1; a.ksplit = H_;
        a.alpha = 0.08838834764831845f;
        hm_gemm<false, false, true, true><<<dim3(16, 16, 4), 256, DSM_BYTES>>>(a);
    }

    // 8: O~ = P V   (unnormalized; single-term fp16 P, split-K x8, atomics)
    {
        TCArgs a{};
        a.Ah = Sh; a.Al = Sh;
        a.Bh0 = vTh; a.Bh1 = vTh; a.Bh2 = vTh;
        a.C0 = o; a.C1 = o; a.C2 = o;
        a.sAz = (long)T_*T_; a.sBz = (long)H_*T_; a.sCz = (long)T_*H_;
        a.lda = T_; a.ldb = T_; a.ldc = H_;
        a.M = T_; a.K = T_; a.nxb = 1; a.nsplit = 8; a.ksplit = 256;
        a.alpha = 1.f;
        hm_gemm<false, true, false, false><<<dim3(1, 16, 32), 256, DSM_BYTES>>>(a);
    }

    split_o<<<512, 256>>>();                                           // 9 (normalize + split)

    // 10: output MoE combine (gathered, weighted atomic accumulate into out)
    {
        TCArgs a{};
        a.Ah = oh; a.Al = ol;
        a.Bh0 = woh; a.Bh1 = woh; a.Bh2 = woh;
        a.C0 = outp; a.C1 = outp; a.C2 = outp;
        a.sAz = 0; a.sBz = (long)C_*H_; a.sCz = 0;
        a.lda = H_; a.ldb = H_; a.ldc = C_;
        a.M = N_; a.K = H_; a.nxb = 8; a.nsplit = 1; a.ksplit = H_;
        a.alpha = 1.f; a.cnt = cnt; a.idxB = idx; a.wtB = wt;
        hm_gemm<true, true, true, false><<<dim3(8, 64, 16), 256, DSM_BYTES>>>(a);
    }
}

// round 17
// speedup vs baseline: 1.2345x; 1.0246x over previous
#include <cuda_runtime.h>
#include <cuda_fp16.h>
#include <math.h>
#include <stdint.h>

#define B_ 4
#define T_ 2048
#define C_ 1024
#define H_ 128
#define E_ 16
#define N_ (B_*T_)   /* 8192 tokens */

// ---------------- scratch (allocation-free: __device__ globals) ----------------
__device__ float g_q[(size_t)N_*H_];
__device__ float g_k[(size_t)N_*H_];
__device__ float g_v[(size_t)N_*H_];
__device__ float g_o[(size_t)N_*H_];
__device__ float g_rsum[N_];                      // attention row sums (exp)

__device__ half g_xh[(size_t)N_*C_],  g_xl[(size_t)N_*C_];
__device__ half g_qh[(size_t)N_*H_],  g_ql[(size_t)N_*H_];
__device__ half g_kh[(size_t)N_*H_];
__device__ half g_vTh[(size_t)N_*H_];                         // [B][H][T]
__device__ half g_oh[(size_t)N_*H_],  g_ol[(size_t)N_*H_];
__device__ half g_Sh[(size_t)B_*T_*T_];                       // unnormalized exp(s-8)
__device__ half g_wqh[(size_t)E_*H_*C_];                      // [E][H][C]
__device__ half g_wkh[(size_t)E_*H_*C_];
__device__ half g_wvh[(size_t)E_*H_*C_];
__device__ half g_woh[(size_t)E_*C_*H_];                      // [E][C][H]

__device__ int   g_cnt[E_];
__device__ int   g_idx[(size_t)E_*N_];
__device__ float g_wt[(size_t)E_*N_];
__device__ float g_invsn[E_];
__device__ float g_sig[E_];

// ---------------- mma.sync / ldmatrix / cp.async helpers (baseline PTX) ---------
#define MMA16816(d, A0, A1, A2, A3, Bv0, Bv1) \
    asm volatile("mma.sync.aligned.m16n8k16.row.col.f32.f16.f16.f32 " \
        "{%0,%1,%2,%3},{%4,%5,%6,%7},{%8,%9},{%0,%1,%2,%3};" \
        : "+f"((d)[0]), "+f"((d)[1]), "+f"((d)[2]), "+f"((d)[3]) \
        : "r"(A0), "r"(A1), "r"(A2), "r"(A3), "r"(Bv0), "r"(Bv1))

#define LDSM4(r0, r1, r2, r3, addr) \
    asm volatile("ldmatrix.sync.aligned.m8n8.x4.shared.b16 {%0,%1,%2,%3}, [%4];" \
        : "=r"(r0), "=r"(r1), "=r"(r2), "=r"(r3) : "r"(addr))

#define CPA16(dst, src) \
    asm volatile("cp.async.cg.shared.global [%0], [%1], 16;" :: "r"(dst), "l"(src))

__device__ __forceinline__ uint32_t smem_u32(const void* p) {
    uint32_t a;
    asm("{ .reg .u64 t; cvta.to.shared.u64 t, %1; cvt.u32.u64 %0, t; }" : "=r"(a) : "l"(p));
    return a;
}

__device__ __forceinline__ void split_f32(float v, half& h, half& l) {
    h = __float2half_rn(v);
    l = __float2half_rn(v - __half2float(h));
}

// ---------------- HMMA GEMM -------------------------------------------------------
// TWOTERM: D = (Ah+Al) * Bh ; else D = Ah * Bh
// EXPEPI : epilogue stores exp(alpha*acc - 8) to fp16 D and row-sums to rsum
struct TCArgs {
    const half *Ah, *Al;
    const half *Bh0, *Bh1, *Bh2;
    float *C0, *C1, *C2;
    half  *D;
    float *rsum;
    long sAz, sBz, sCz;
    int  lda, ldb, ldc;
    int  M, K, nxb, nsplit, ksplit;
    float alpha;
    const int* cnt; const int* idxB; const float* wtB;
};

#define PITCH 20   /* row pitch in b32 units: 16 b32 (32 fp16) + 4 pad */
#define TILE_U32 (128*PITCH)
#define DSM_BYTES (3*3*TILE_U32*4)   /* 3 stages x 3 tiles = 92160 B */

template<bool GATHER, bool ATOMIC, bool TWOTERM, bool EXPEPI>
__global__ void __launch_bounds__(256, 2) hm_gemm(TCArgs a)
{
    int zb  = blockIdx.z / a.nsplit;
    int sp  = blockIdx.z % a.nsplit;
    int mat = blockIdx.x / a.nxb;
    int n0  = (blockIdx.x % a.nxb) * 128;

    int Mz = a.M;
    const int*   gidx = nullptr;
    const float* gwt  = nullptr;
    if (GATHER) {
        Mz   = a.cnt[zb];
        gidx = a.idxB + (size_t)zb * N_;
        gwt  = a.wtB  + (size_t)zb * N_;
    }
    int m0 = blockIdx.y * 128;
    if (m0 >= Mz) return;

    const half* Ah = a.Ah + (size_t)zb * a.sAz;
    const half* Al = a.Al + (size_t)zb * a.sAz;
    const half* Bh = (mat == 0 ? a.Bh0 : mat == 1 ? a.Bh1 : a.Bh2) + (size_t)zb * a.sBz;
    float*      C  = (mat == 0 ? a.C0  : mat == 1 ? a.C1  : a.C2)  + (size_t)zb * a.sCz;

    extern __shared__ uint32_t dsm[];
    uint32_t smbase = smem_u32(dsm);

    __shared__ int   s_idx[128];
    __shared__ float s_wt[128];

    int tid  = threadIdx.x;
    int lane = tid & 31, wid = tid >> 5;
    int g = lane >> 2, t = lane & 3;
    int wm = wid & 1, wn = wid >> 1;          // warp grid 2 (m) x 4 (n)
    int mbw = wm * 64, nbw = wn * 32;

    if (GATHER) {
        for (int i = tid; i < 128; i += 256) {
            int r = m0 + i;
            bool v = r < Mz;
            s_idx[i] = v ? gidx[r] : 0;
            s_wt[i]  = v ? gwt[r] : 0.f;
        }
    }
    __syncthreads();

    float acc[4][4][4];
    #pragma unroll
    for (int i = 0; i < 4; i++)
        #pragma unroll
        for (int j = 0; j < 4; j++)
            #pragma unroll
            for (int c = 0; c < 4; c++) acc[i][j][c] = 0.f;

    int kb = sp * a.ksplit;
    int ke = kb + a.ksplit; if (ke > a.K) ke = a.K;
    int nch = (ke - kb) >> 5;

    // per-thread global load coordinates (fixed across k-chunks)
    int f0row = tid >> 2,          f0kq = tid & 3;
    int f1row = (tid + 256) >> 2,  f1kq = (tid + 256) & 3;
    long ar0 = GATHER ? (long)s_idx[f0row] : (long)(m0 + f0row);
    long ar1 = GATHER ? (long)s_idx[f1row] : (long)(m0 + f1row);
    long br0 = (long)(n0 + f0row), br1 = (long)(n0 + f1row);
    uint32_t so0 = (uint32_t)(f0row * PITCH + f0kq * 4) * 4u;
    uint32_t so1 = (uint32_t)(f1row * PITCH + f1kq * 4) * 4u;

    // ldmatrix lane-address offsets (bytes)
    int jj = lane >> 3, rr = lane & 7;
    uint32_t aoff = (uint32_t)(((jj & 1) * 8 + rr) * PITCH + (jj >> 1) * 4) * 4u;
    uint32_t boff = (uint32_t)(((jj >> 1) * 8 + rr) * PITCH + (jj & 1) * 4) * 4u;
    uint32_t baseA = smbase + (uint32_t)(mbw * PITCH) * 4u + aoff;
    uint32_t baseB = smbase + (uint32_t)(nbw * PITCH) * 4u + boff;
    const uint32_t TB = (uint32_t)TILE_U32 * 4u;   // tile stride in bytes

    // chunk loader into stage s (tiles: Ah, [Al], Bh)
    auto load_chunk = [&](int k0, int s) {
        uint32_t bb = (uint32_t)(s * 3) * TB;
        CPA16(smbase + bb + 0*TB + so0, Ah + ar0 * (long)a.lda + k0 + f0kq * 8);
        CPA16(smbase + bb + 0*TB + so1, Ah + ar1 * (long)a.lda + k0 + f1kq * 8);
        if (TWOTERM) {
            CPA16(smbase + bb + 1*TB + so0, Al + ar0 * (long)a.lda + k0 + f0kq * 8);
            CPA16(smbase + bb + 1*TB + so1, Al + ar1 * (long)a.lda + k0 + f1kq * 8);
        }
        CPA16(smbase + bb + 2*TB + so0, Bh + br0 * (long)a.ldb + k0 + f0kq * 8);
        CPA16(smbase + bb + 2*TB + so1, Bh + br1 * (long)a.ldb + k0 + f1kq * 8);
    };

    // 3-stage pipeline prologue
    load_chunk(kb, 0);
    asm volatile("cp.async.commit_group;" ::: "memory");
    if (nch > 1) {
        load_chunk(kb + 32, 1);
        asm volatile("cp.async.commit_group;" ::: "memory");
    }

    int stage = 0;
    for (int i = 0; i < nch; i++) {
        if (i < nch - 1) asm volatile("cp.async.wait_group 1;" ::: "memory");
        else             asm volatile("cp.async.wait_group 0;" ::: "memory");
        __syncthreads();

        if (i + 2 < nch) {
            int s2 = stage + 2; if (s2 >= 3) s2 -= 3;
            load_chunk(kb + (i + 2) * 32, s2);
            asm volatile("cp.async.commit_group;" ::: "memory");
        }

        uint32_t bb = (uint32_t)(stage * 3) * TB;
        uint32_t bAh = baseA + bb + 0*TB, bAl = baseA + bb + 1*TB;
        uint32_t bBh = baseB + bb + 2*TB;

        #pragma unroll
        for (int kk = 0; kk < 2; kk++) {
            uint32_t kadd = (uint32_t)(kk * 8) * 4u;
            uint32_t bh[4][2];
            #pragma unroll
            for (int np = 0; np < 2; np++) {
                uint32_t ba = (uint32_t)(np * 16 * PITCH) * 4u + kadd;
                LDSM4(bh[2*np][0], bh[2*np][1], bh[2*np+1][0], bh[2*np+1][1], bBh + ba);
            }
            #pragma unroll
            for (int mt = 0; mt < 4; mt++) {
                uint32_t ma = (uint32_t)(mt * 16 * PITCH) * 4u + kadd;
                uint32_t ah0, ah1, ah2, ah3;
                LDSM4(ah0, ah1, ah2, ah3, bAh + ma);
                if (TWOTERM) {
                    uint32_t al0, al1, al2, al3;
                    LDSM4(al0, al1, al2, al3, bAl + ma);
                    #pragma unroll
                    for (int nt = 0; nt < 4; nt++) {
                        MMA16816(acc[mt][nt], ah0, ah1, ah2, ah3, bh[nt][0], bh[nt][1]);
                        MMA16816(acc[mt][nt], al0, al1, al2, al3, bh[nt][0], bh[nt][1]);
                    }
                } else {
                    #pragma unroll
                    for (int nt = 0; nt < 4; nt++)
                        MMA16816(acc[mt][nt], ah0, ah1, ah2, ah3, bh[nt][0], bh[nt][1]);
                }
            }
        }
        stage = stage + 1; if (stage >= 3) stage -= 3;
    }

    // ---------------- epilogue ----------------
    if (EXPEPI) {
        half*  Dp = a.D    + (size_t)zb * (size_t)T_ * T_;
        float* rs = a.rsum + (size_t)zb * T_;
        #pragma unroll
        for (int mt = 0; mt < 4; mt++) {
            #pragma unroll
            for (int half_ = 0; half_ < 2; half_++) {
                int lr = mbw + mt * 16 + g + half_ * 8;
                long orow = m0 + lr;
                half* dp = Dp + orow * (long)T_ + n0 + nbw;
                float rsl = 0.f;
                #pragma unroll
                for (int nt = 0; nt < 4; nt++) {
                    int col = nt * 8 + 2 * t;
                    float p0 = __expf(acc[mt][nt][half_ * 2 + 0] * a.alpha - 8.f);
                    float p1 = __expf(acc[mt][nt][half_ * 2 + 1] * a.alpha - 8.f);
                    *(__half2*)(dp + col) = __halves2half2(__float2half_rn(p0), __float2half_rn(p1));
                    rsl += p0 + p1;
                }
                rsl += __shfl_xor_sync(0xffffffffu, rsl, 1);
                rsl += __shfl_xor_sync(0xffffffffu, rsl, 2);
                if (t == 0) atomicAdd(rs + orow, rsl);
            }
        }
    } else {
        #pragma unroll
        for (int mt = 0; mt < 4; mt++) {
            #pragma unroll
            for (int half_ = 0; half_ < 2; half_++) {
                int lr = mbw + mt * 16 + g + half_ * 8;
                bool rv; long orow; float sc;
                if (GATHER) { rv = (m0 + lr) < Mz; orow = s_idx[lr]; sc = a.alpha * s_wt[lr]; }
                else        { rv = true;           orow = m0 + lr;   sc = a.alpha; }
                if (rv) {
                    float* cp = C + orow * (long)a.ldc + n0 + nbw;
                    #pragma unroll
                    for (int nt = 0; nt < 4; nt++) {
                        int col = nt * 8 + 2 * t;
                        float v0 = acc[mt][nt][half_ * 2 + 0] * sc;
                        float v1 = acc[mt][nt][half_ * 2 + 1] * sc;
                        if (ATOMIC) { atomicAdd(cp + col, v0); atomicAdd(cp + col + 1, v1); }
                        else        { float2 vv; vv.x = v0; vv.y = v1; *(float2*)(cp + col) = vv; }
                    }
                }
            }
        }
    }
}

// ---------------- sim-matrix column norms + sigmoid(gates) + counter reset -------
__global__ void prep_kernel(const float* __restrict__ sim, const float* __restrict__ gates) {
    int e = threadIdx.x >> 5, lane = threadIdx.x & 31;
    if (threadIdx.x < E_) g_cnt[threadIdx.x] = 0;
    float s = 0.f;
    for (int c = lane; c < C_; c += 32) { float v = sim[(size_t)c*E_ + e]; s += v*v; }
    #pragma unroll
    for (int o = 16; o > 0; o >>= 1) s += __shfl_xor_sync(0xffffffffu, s, o);
    if (lane == 0) {
        g_invsn[e] = 1.0f / fmaxf(sqrtf(s), 1e-12f);
        g_sig[e]   = 1.0f / (1.0f + expf(-gates[e]));
    }
}

// ---------------- gating (one warp per token) ------------------------------------
__global__ void gating_kernel(const float* __restrict__ x, const float* __restrict__ sim) {
    int tok  = blockIdx.x * (blockDim.x >> 5) + (threadIdx.x >> 5);
    int lane = threadIdx.x & 31;
    if (tok >= N_) return;
    const float* xr = x + (size_t)tok * C_;

    float dot[E_];
    #pragma unroll
    for (int e = 0; e < E_; e++) dot[e] = 0.f;
    float nrm = 0.f;
    for (int c = lane; c < C_; c += 32) {
        float xv = xr[c];
        nrm += xv * xv;
        const float4* s4 = (const float4*)(sim + (size_t)c * E_);
        float4 r0 = s4[0], r1 = s4[1], r2 = s4[2], r3 = s4[3];
        dot[0]+=xv*r0.x; dot[1]+=xv*r0.y; dot[2]+=xv*r0.z; dot[3]+=xv*r0.w;
        dot[4]+=xv*r1.x; dot[5]+=xv*r1.y; dot[6]+=xv*r1.z; dot[7]+=xv*r1.w;
        dot[8]+=xv*r2.x; dot[9]+=xv*r2.y; dot[10]+=xv*r2.z; dot[11]+=xv*r2.w;
        dot[12]+=xv*r3.x; dot[13]+=xv*r3.y; dot[14]+=xv*r3.z; dot[15]+=xv*r3.w;
    }
    #pragma unroll
    for (int o = 16; o > 0; o >>= 1) {
        nrm += __shfl_xor_sync(0xffffffffu, nrm, o);
        #pragma unroll
        for (int e = 0; e < E_; e++) dot[e] += __shfl_xor_sync(0xffffffffu, dot[e], o);
    }
    float invx = 1.0f / fmaxf(sqrtf(nrm), 1e-12f);

    float logit[E_], gated[E_];
    unsigned msk = 0u;
    #pragma unroll
    for (int e = 0; e < E_; e++) {
        logit[e] = dot[e] * invx * g_invsn[e] - g_sig[e];
        gated[e] = fmaxf(logit[e], 0.f);
        if (logit[e] > 0.f) msk |= (1u << e);
    }
    if (msk == 0u) {
        float m1 = -3.4e38f; int i1 = 0;
        #pragma unroll
        for (int e = 0; e < E_; e++) if (logit[e] > m1) { m1 = logit[e]; i1 = e; }
        float m2 = -3.4e38f; int i2 = 0;
        #pragma unroll
        for (int e = 0; e < E_; e++) if (e != i1 && logit[e] > m2) { m2 = logit[e]; i2 = e; }
        msk = (1u << i1) | (1u << i2);
    }
    float mx = -3.4e38f;
    #pragma unroll
    for (int e = 0; e < E_; e++) if ((msk >> e) & 1u) mx = fmaxf(mx, gated[e]);
    float wv[E_]; float sum = 0.f;
    #pragma unroll
    for (int e = 0; e < E_; e++) {
        wv[e] = ((msk >> e) & 1u) ? expf(gated[e] - mx) : 0.f;
        sum += wv[e];
    }
    float inv = 1.0f / sum;
    #pragma unroll
    for (int e = 0; e < E_; e++) {
        if (lane == e && ((msk >> e) & 1u)) {
            int pos = atomicAdd(&g_cnt[e], 1);
            g_idx[(size_t)e * N_ + pos] = tok;
            g_wt [(size_t)e * N_ + pos] = wv[e] * inv;
        }
    }
}

// ---------------- fused operand prep ---------------------------------------------
__global__ void prep_operands(const float* __restrict__ qp, const float* __restrict__ kp,
                              const float* __restrict__ vp, const float* __restrict__ op,
                              const float* __restrict__ x,  float* __restrict__ out)
{
    int z = blockIdx.z;
    int tid = threadIdx.x;
    if (z < 64) {
        __shared__ float tsm[32][33];
        int e = z >> 2, mat = z & 3;
        const float* in;
        half* oh;
        int R, Cc, c0, r0;
        if (mat == 0)      { in = qp; oh = g_wqh; }
        else if (mat == 1) { in = kp; oh = g_wkh; }
        else if (mat == 2) { in = vp; oh = g_wvh; }
        else               { in = op; oh = g_woh; }
        if (mat < 3) { R = C_; Cc = H_; c0 = blockIdx.x * 32; r0 = blockIdx.y * 32; }
        else         { R = H_; Cc = C_; c0 = blockIdx.y * 32; r0 = blockIdx.x * 32; }
        size_t zo = (size_t)e * R * Cc;
        in += zo; oh += zo;
        int tx = tid & 31, ty = tid >> 5;
        #pragma unroll
        for (int i = ty; i < 32; i += 8) tsm[i][tx] = in[(size_t)(r0 + i) * Cc + c0 + tx];
        __syncthreads();
        #pragma unroll
        for (int i = ty; i < 32; i += 8)
            oh[(size_t)(c0 + i) * R + r0 + tx] = __float2half_rn(tsm[tx][i]);
    } else {
        long flat = (long)(z - 64) * 128 + blockIdx.y * 4 + blockIdx.x;  // 0..4095
        const long STRIDE = 2048L * 256;
        if (flat < 2048) {
            long i = flat * 256 + tid;
            long n4 = (long)N_ * C_ / 4;
            for (; i < n4; i += STRIDE) {
                float4 v = ((const float4*)x)[i];
                half h0, l0, h1, l1, h2, l2, h3, l3;
                split_f32(v.x, h0, l0); split_f32(v.y, h1, l1);
                split_f32(v.z, h2, l2); split_f32(v.w, h3, l3);
                ((__half2*)g_xh)[2*i]   = __halves2half2(h0, h1);
                ((__half2*)g_xh)[2*i+1] = __halves2half2(h2, h3);
                ((__half2*)g_xl)[2*i]   = __halves2half2(l0, l1);
                ((__half2*)g_xl)[2*i+1] = __halves2half2(l2, l3);
            }
        } else {
            long i = (flat - 2048) * 256 + tid;
            float4 zf = make_float4(0.f, 0.f, 0.f, 0.f);
            long nqkv = (long)N_ * H_ / 4;
            for (long j = i; j < nqkv; j += STRIDE) {
                ((float4*)g_q)[j] = zf; ((float4*)g_k)[j] = zf;
                ((float4*)g_v)[j] = zf; ((float4*)g_o)[j] = zf;
            }
            long nout = (long)N_ * C_ / 4;
            for (long j = i; j < nout; j += STRIDE) ((float4*)out)[j] = zf;
            for (long j = i; j < N_; j += STRIDE) g_rsum[j] = 0.f;
        }
    }
}

// ---------------- split q (hi/lo) + convert k (hi) -------------------------------
__global__ void split_qk() {
    long i  = (long)blockIdx.x * blockDim.x + threadIdx.x;
    long st = (long)gridDim.x * blockDim.x;
    long n4 = (long)N_ * H_ / 4;
    for (; i < n4; i += st) {
        float4 qv = ((const float4*)g_q)[i];
        half h0, l0, h1, l1, h2, l2, h3, l3;
        split_f32(qv.x, h0, l0); split_f32(qv.y, h1, l1);
        split_f32(qv.z, h2, l2); split_f32(qv.w, h3, l3);
        ((__half2*)g_qh)[2*i]   = __halves2half2(h0, h1);
        ((__half2*)g_qh)[2*i+1] = __halves2half2(h2, h3);
        ((__half2*)g_ql)[2*i]   = __halves2half2(l0, l1);
        ((__half2*)g_ql)[2*i+1] = __halves2half2(l2, l3);
        float4 kv = ((const float4*)g_k)[i];
        ((__half2*)g_kh)[2*i]   = __halves2half2(__float2half_rn(kv.x), __float2half_rn(kv.y));
        ((__half2*)g_kh)[2*i+1] = __halves2half2(__float2half_rn(kv.z), __float2half_rn(kv.w));
    }
}

// ---------------- normalize o by rsum + split hi/lo ------------------------------
__global__ void split_o() {
    long i  = (long)blockIdx.x * blockDim.x + threadIdx.x;
    long st = (long)gridDim.x * blockDim.x;
    long n4 = (long)N_ * H_ / 4;
    for (; i < n4; i += st) {
        long row = i >> 5;                      // 32 float4 per 128-elem row
        float inv = 1.0f / g_rsum[row];
        float4 v = ((const float4*)g_o)[i];
        v.x *= inv; v.y *= inv; v.z *= inv; v.w *= inv;
        half h0, l0, h1, l1, h2, l2, h3, l3;
        split_f32(v.x, h0, l0); split_f32(v.y, h1, l1);
        split_f32(v.z, h2, l2); split_f32(v.w, h3, l3);
        ((__half2*)g_oh)[2*i]   = __halves2half2(h0, h1);
        ((__half2*)g_oh)[2*i+1] = __halves2half2(h2, h3);
        ((__half2*)g_ol)[2*i]   = __halves2half2(l0, l1);
        ((__half2*)g_ol)[2*i+1] = __halves2half2(l2, l3);
    }
}

// ---------------- transpose v -> vT (fp16 hi only), per batch --------------------
__global__ void tsplit_h() {
    __shared__ float tsm[32][33];
    size_t zo = (size_t)blockIdx.z * T_ * H_;
    const float* in = g_v + zo;
    half* oh = g_vTh + zo;
    int c0 = blockIdx.x * 32, r0 = blockIdx.y * 32;
    int tx = threadIdx.x, ty = threadIdx.y;
    #pragma unroll
    for (int i = ty; i < 32; i += 8) tsm[i][tx] = in[(size_t)(r0 + i) * H_ + c0 + tx];
    __syncthreads();
    #pragma unroll
    for (int i = ty; i < 32; i += 8)
        oh[(size_t)(c0 + i) * T_ + r0 + tx] = __float2half_rn(tsm[tx][i]);
}

// ---------------- launch ---------------------------------------------------------
extern "C" void kernel_launch(void* const* d_in, const int* in_sizes, int n_in,
                              void* d_out, int out_size)
{
    const float* x     = (const float*)d_in[0];
    const float* sim   = (const float*)d_in[1];
    const float* gates = (const float*)d_in[2];
    const float* qp    = (const float*)d_in[3];
    const float* kp    = (const float*)d_in[4];
    const float* vp    = (const float*)d_in[5];
    const float* op    = (const float*)d_in[6];
    float* outp = (float*)d_out;

    float *q, *k, *v, *o, *rsum, *wt;
    int *cnt, *idx;
    half *xh, *xl, *qh, *ql, *kh, *vTh, *oh, *ol, *Sh;
    half *wqh, *wkh, *wvh, *woh;
    cudaGetSymbolAddress((void**)&q, g_q);     cudaGetSymbolAddress((void**)&k, g_k);
    cudaGetSymbolAddress((void**)&v, g_v);     cudaGetSymbolAddress((void**)&o, g_o);
    cudaGetSymbolAddress((void**)&rsum, g_rsum);
    cudaGetSymbolAddress((void**)&cnt, g_cnt); cudaGetSymbolAddress((void**)&idx, g_idx);
    cudaGetSymbolAddress((void**)&wt, g_wt);
    cudaGetSymbolAddress((void**)&xh, g_xh);   cudaGetSymbolAddress((void**)&xl, g_xl);
    cudaGetSymbolAddress((void**)&qh, g_qh);   cudaGetSymbolAddress((void**)&ql, g_ql);
    cudaGetSymbolAddress((void**)&kh, g_kh);
    cudaGetSymbolAddress((void**)&vTh, g_vTh);
    cudaGetSymbolAddress((void**)&oh, g_oh);   cudaGetSymbolAddress((void**)&ol, g_ol);
    cudaGetSymbolAddress((void**)&Sh, g_Sh);
    cudaGetSymbolAddress((void**)&wqh, g_wqh); cudaGetSymbolAddress((void**)&wkh, g_wkh);
    cudaGetSymbolAddress((void**)&wvh, g_wvh); cudaGetSymbolAddress((void**)&woh, g_woh);

    cudaFuncSetAttribute(hm_gemm<true,  true,  true,  false>, cudaFuncAttributeMaxDynamicSharedMemorySize, DSM_BYTES);
    cudaFuncSetAttribute(hm_gemm<false, false, true,  true >, cudaFuncAttributeMaxDynamicSharedMemorySize, DSM_BYTES);
    cudaFuncSetAttribute(hm_gemm<false, true,  false, false>, cudaFuncAttributeMaxDynamicSharedMemorySize, DSM_BYTES);

    // side stream + events (created once, outside capture; host-side only)
    static cudaStream_t sB = nullptr;
    static cudaEvent_t evA = nullptr, evB = nullptr, evC = nullptr, evD = nullptr;
    if (sB == nullptr) {
        cudaStreamCreateWithFlags(&sB, cudaStreamNonBlocking);
        cudaEventCreateWithFlags(&evA, cudaEventDisableTiming);
        cudaEventCreateWithFlags(&evB, cudaEventDisableTiming);
        cudaEventCreateWithFlags(&evC, cudaEventDisableTiming);
        cudaEventCreateWithFlags(&evD, cudaEventDisableTiming);
    }

    prep_kernel<<<1, 512>>>(sim, gates);                                   // main
    cudaEventRecord(evA, 0);
    cudaStreamWaitEvent(sB, evA, 0);
    gating_kernel<<<N_/8, 256>>>(x, sim);                                  // main
    prep_operands<<<dim3(4, 32, 96), 256, 0, sB>>>(qp, kp, vp, op, x, outp); // side
    cudaEventRecord(evB, sB);
    cudaStreamWaitEvent(0, evB, 0);                                        // join

    // QKV MoE dispatch (gathered, weighted atomic accumulate, split-K x2)
    {
        TCArgs a{};
        a.Ah = xh; a.Al = xl;
        a.Bh0 = wqh; a.Bh1 = wkh; a.Bh2 = wvh;
        a.C0 = q; a.C1 = k; a.C2 = v;
        a.sAz = 0; a.sBz = (long)H_*C_; a.sCz = 0;
        a.lda = C_; a.ldb = C_; a.ldc = H_;
        a.M = N_; a.K = C_; a.nxb = 1; a.nsplit = 2; a.ksplit = 512;
        a.alpha = 1.f; a.cnt = cnt; a.idxB = idx; a.wtB = wt;
        hm_gemm<true, true, true, false><<<dim3(3, 64, 32), 256, DSM_BYTES>>>(a);
    }

    cudaEventRecord(evC, 0);
    cudaStreamWaitEvent(sB, evC, 0);
    split_qk<<<512, 256>>>();                                              // main
    tsplit_h<<<dim3(H_/32, T_/32, B_), dim3(32,8), 0, sB>>>();             // side

    // P = exp(Q K^T / sqrt(H) - 8)  (fused softmax epilogue; rowsums to rsum)
    {
        TCArgs a{};
        a.Ah = qh; a.Al = ql;
        a.Bh0 = kh; a.Bh1 = kh; a.Bh2 = kh;
        a.C0 = outp; a.C1 = outp; a.C2 = outp;   // unused in EXPEPI
        a.D = Sh; a.rsum = rsum;
        a.sAz = (long)T_*H_; a.sBz = (long)T_*H_; a.sCz = 0;
        a.lda = H_; a.ldb = H_; a.ldc = T_;
        a.M = T_; a.K = H_; a.nxb = 16; a.nsplit = 1; a.ksplit = H_;
        a.alpha = 0.08838834764831845f;
        hm_gemm<false, false, true, true><<<dim3(16, 16, 4), 256, DSM_BYTES>>>(a);
    }

    cudaEventRecord(evD, sB);
    cudaStreamWaitEvent(0, evD, 0);                                        // join v-transpose

    // O~ = P V   (unnormalized; single-term fp16 P, split-K x8, atomics)
    {
        TCArgs a{};
        a.Ah = Sh; a.Al = Sh;
        a.Bh0 = vTh; a.Bh1 = vTh; a.Bh2 = vTh;
        a.C0 = o; a.C1 = o; a.C2 = o;
        a.sAz = (long)T_*T_; a.sBz = (long)H_*T_; a.sCz = (long)T_*H_;
        a.lda = T_; a.ldb = T_; a.ldc = H_;
        a.M = T_; a.K = T_; a.nxb = 1; a.nsplit = 8; a.ksplit = 256;
        a.alpha = 1.f;
        hm_gemm<false, true, false, false><<<dim3(1, 16, 32), 256, DSM_BYTES>>>(a);
    }

    split_o<<<512, 256>>>();                                               // normalize + split

    // output MoE combine (gathered, weighted atomic accumulate into out)
    {
        TCArgs a{};
        a.Ah = oh; a.Al = ol;
        a.Bh0 = woh; a.Bh1 = woh; a.Bh2 = woh;
        a.C0 = outp; a.C1 = outp; a.C2 = outp;
        a.sAz = 0; a.sBz = (long)C_*H_; a.sCz = 0;
        a.lda = H_; a.ldb = H_; a.ldc = C_;
        a.M = N_; a.K = H_; a.nxb = 8; a.nsplit = 1; a.ksplit = H_;
        a.alpha = 1.f; a.cnt = cnt; a.idxB = idx; a.wtB = wt;
        hm_gemm<true, true, true, false><<<dim3(8, 64, 16), 256, DSM_BYTES>>>(a);
    }
}